// round 1
// baseline (speedup 1.0000x reference)
#include <cuda_runtime.h>
#include <cuda_bf16.h>
#include <cstdint>

// Problem constants
#define LNUM 2
#define Bsz 4
#define Pn  256
#define Hd  768
#define En  2
#define Nst 16
#define Kc4 4
#define DIN (En*Hd)          // 1536
#define Rr  48               // (H+15)//16 = 48
#define Tt  (Bsz*Pn)         // 1024
#define D2  (2*DIN)          // 3072
#define XDBW (Rr + 2*Nst)    // 80

// Scratch (device globals; no allocation allowed)
__device__ float g_x   [Tt*Hd];
__device__ float g_hn  [Tt*Hd];
__device__ float g_proj[Tt*D2];
__device__ float g_hs  [Tt*DIN];
__device__ float g_xdb [Tt*XDBW];
__device__ float g_dt  [Tt*DIN];
__device__ float g_y   [Tt*DIN];

// ---------------- RMSNorm ----------------
__global__ void rmsnorm_kernel(const float* __restrict__ x,
                               const float* __restrict__ w,
                               float* __restrict__ out) {
    int t = blockIdx.x;
    const float* row = x + (size_t)t * Hd;
    float s = 0.f;
    for (int i = threadIdx.x; i < Hd; i += blockDim.x) {
        float v = row[i];
        s += v * v;
    }
    __shared__ float sh[32];
    int lane = threadIdx.x & 31, wp = threadIdx.x >> 5;
    #pragma unroll
    for (int o = 16; o; o >>= 1) s += __shfl_down_sync(0xffffffffu, s, o);
    if (lane == 0) sh[wp] = s;
    __syncthreads();
    float tot = 0.f;
    if (wp == 0) {
        tot = (lane < (blockDim.x >> 5)) ? sh[lane] : 0.f;
        #pragma unroll
        for (int o = 16; o; o >>= 1) tot += __shfl_down_sync(0xffffffffu, tot, o);
        if (lane == 0) sh[0] = tot;
    }
    __syncthreads();
    float inv = rsqrtf(sh[0] / (float)Hd + 1e-5f);
    for (int i = threadIdx.x; i < Hd; i += blockDim.x)
        out[(size_t)t * Hd + i] = row[i] * inv * w[i];
}

// ---------------- Generic GEMM: C = A(MxK, lda) * B(NxK, ldb)^T ----------------
// MODE 0: C = AB^T     MODE 1: C = softplus(AB^T + bias)     MODE 2: C += AB^T
#define BM 64
#define BN 64
#define BK 16
template<int MODE>
__global__ void gemm_tn(const float* __restrict__ A, int lda,
                        const float* __restrict__ B, int ldb,
                        float* __restrict__ C, int ldc,
                        int M, int Nc, int Kc,
                        const float* __restrict__ bias) {
    __shared__ float As[BK][BM + 4];
    __shared__ float Bs[BK][BN + 4];
    int bm = blockIdx.y * BM, bn = blockIdx.x * BN;
    int tid = threadIdx.x;
    int tx = tid & 15;        // N direction
    int ty = tid >> 4;        // M direction
    float acc[4][4];
    #pragma unroll
    for (int i = 0; i < 4; i++)
        #pragma unroll
        for (int j = 0; j < 4; j++) acc[i][j] = 0.f;

    for (int k0 = 0; k0 < Kc; k0 += BK) {
        #pragma unroll
        for (int i = tid; i < BM * BK; i += 256) {
            int r = i >> 4, c = i & 15;
            int gr = bm + r, gc = k0 + c;
            As[c][r] = (gr < M && gc < Kc) ? A[(size_t)gr * lda + gc] : 0.f;
        }
        #pragma unroll
        for (int i = tid; i < BN * BK; i += 256) {
            int r = i >> 4, c = i & 15;
            int gr = bn + r, gc = k0 + c;
            Bs[c][r] = (gr < Nc && gc < Kc) ? B[(size_t)gr * ldb + gc] : 0.f;
        }
        __syncthreads();
        #pragma unroll
        for (int k = 0; k < BK; k++) {
            float a[4], b[4];
            #pragma unroll
            for (int i = 0; i < 4; i++) a[i] = As[k][ty * 4 + i];
            #pragma unroll
            for (int j = 0; j < 4; j++) b[j] = Bs[k][tx * 4 + j];
            #pragma unroll
            for (int i = 0; i < 4; i++)
                #pragma unroll
                for (int j = 0; j < 4; j++) acc[i][j] += a[i] * b[j];
        }
        __syncthreads();
    }

    #pragma unroll
    for (int i = 0; i < 4; i++) {
        int row = bm + ty * 4 + i;
        if (row >= M) continue;
        #pragma unroll
        for (int j = 0; j < 4; j++) {
            int col = bn + tx * 4 + j;
            if (col >= Nc) continue;
            size_t o = (size_t)row * ldc + col;
            float v = acc[i][j];
            if (MODE == 0) {
                C[o] = v;
            } else if (MODE == 1) {
                v += bias[col];
                // stable softplus
                float sp = (v > 0.f) ? v + log1pf(expf(-v)) : log1pf(expf(v));
                C[o] = sp;
            } else {
                C[o] += v;
            }
        }
    }
}

// ---------------- Conv shift + silu ----------------
__global__ void conv_kernel(const float* __restrict__ conv_states_l,
                            const float* __restrict__ conv_w_l,
                            const float* __restrict__ conv_b_l,
                            float* __restrict__ out_conv_l) {
    int idx = blockIdx.x * blockDim.x + threadIdx.x;
    if (idx >= Tt * DIN) return;
    int t = idx / DIN, d = idx - t * DIN;
    float4 cs = *(const float4*)(conv_states_l + (size_t)idx * 4);
    float hsv = g_proj[(size_t)t * D2 + d];
    float4 nc = make_float4(cs.y, cs.z, cs.w, hsv);
    *(float4*)(out_conv_l + (size_t)idx * 4) = nc;
    float4 w = *(const float4*)(conv_w_l + (size_t)d * 4);
    float s = nc.x * w.x + nc.y * w.y + nc.z * w.z + nc.w * w.w + conv_b_l[d];
    g_hs[idx] = s / (1.f + expf(-s));   // silu
}

// ---------------- SSM state update + gated output ----------------
__global__ void ssm_kernel(const float* __restrict__ ssm_l,
                           const float* __restrict__ A_log_l,
                           const float* __restrict__ D_l,
                           float* __restrict__ out_ssm_l) {
    __shared__ float Bsh[Nst], Csh[Nst];
    int idx = blockIdx.x * 256 + threadIdx.x;     // DIN % 256 == 0 -> whole block same t
    int t = idx / DIN, d = idx - t * DIN;
    if (threadIdx.x < 2 * Nst) {
        float v = g_xdb[(size_t)t * XDBW + Rr + threadIdx.x];
        if (threadIdx.x < Nst) Bsh[threadIdx.x] = v;
        else Csh[threadIdx.x - Nst] = v;
    }
    __syncthreads();
    float dtv = g_dt[idx];
    float hsv = g_hs[idx];
    const float* Ar = A_log_l + (size_t)d * Nst;
    const float* sr = ssm_l + (size_t)idx * Nst;
    float* so = out_ssm_l + (size_t)idx * Nst;
    float y = 0.f;
    #pragma unroll
    for (int n = 0; n < Nst; n++) {
        float a  = -expf(Ar[n]);
        float dA = expf(dtv * a);
        float ssv = sr[n] * dA + dtv * Bsh[n] * hsv;
        so[n] = ssv;
        y += ssv * Csh[n];
    }
    y += D_l[d] * hsv;
    float g = g_proj[(size_t)t * D2 + DIN + d];
    y *= g / (1.f + expf(-g));          // * silu(gate)
    g_y[idx] = y;
}

extern "C" void kernel_launch(void* const* d_in, const int* in_sizes, int n_in,
                              void* d_out, int out_size) {
    const float* u          = (const float*)d_in[0];
    const float* conv_st    = (const float*)d_in[1];
    const float* ssm_st     = (const float*)d_in[2];
    const float* in_proj_w  = (const float*)d_in[3];
    const float* conv_w     = (const float*)d_in[4];
    const float* conv_b     = (const float*)d_in[5];
    const float* x_proj_w   = (const float*)d_in[6];
    const float* dt_proj_w  = (const float*)d_in[7];
    const float* dt_proj_b  = (const float*)d_in[8];
    const float* A_log      = (const float*)d_in[9];
    const float* D_w        = (const float*)d_in[10];
    const float* out_proj_w = (const float*)d_in[11];
    const float* norm_w     = (const float*)d_in[12];
    const float* norm_f_w   = (const float*)d_in[13];

    float* out_x    = (float*)d_out;
    float* out_conv = out_x + (size_t)Tt * Hd;
    float* out_ssm  = out_conv + (size_t)LNUM * Tt * DIN * Kc4;

    float *xb, *hnb, *projb, *hsb, *xdbb, *dtb, *yb;
    cudaGetSymbolAddress((void**)&xb,    g_x);
    cudaGetSymbolAddress((void**)&hnb,   g_hn);
    cudaGetSymbolAddress((void**)&projb, g_proj);
    cudaGetSymbolAddress((void**)&hsb,   g_hs);
    cudaGetSymbolAddress((void**)&xdbb,  g_xdb);
    cudaGetSymbolAddress((void**)&dtb,   g_dt);
    cudaGetSymbolAddress((void**)&yb,    g_y);

    // x = u
    cudaMemcpyAsync(xb, u, sizeof(float) * (size_t)Tt * Hd, cudaMemcpyDeviceToDevice);

    const int TDN = Tt * DIN;
    dim3 blk256(256);

    for (int l = 0; l < LNUM; l++) {
        const float* ipw = in_proj_w + (size_t)l * D2 * Hd;
        const float* cw  = conv_w   + (size_t)l * DIN * Kc4;
        const float* cb  = conv_b   + (size_t)l * DIN;
        const float* xpw = x_proj_w + (size_t)l * XDBW * DIN;
        const float* dpw = dt_proj_w+ (size_t)l * DIN * Rr;
        const float* dpb = dt_proj_b+ (size_t)l * DIN;
        const float* Al  = A_log    + (size_t)l * DIN * Nst;
        const float* Dl  = D_w      + (size_t)l * DIN;
        const float* opw = out_proj_w + (size_t)l * Hd * DIN;
        const float* csl = conv_st  + (size_t)l * TDN * Kc4;
        const float* ssl = ssm_st   + (size_t)l * TDN * Nst;
        float* ocl = out_conv + (size_t)l * TDN * Kc4;
        float* osl = out_ssm  + (size_t)l * TDN * Nst;

        // 1. hn = rmsnorm(x, norm_w[l])
        rmsnorm_kernel<<<Tt, 256>>>(xb, norm_w + (size_t)l * Hd, hnb);

        // 2. proj = hn @ in_proj_w[l]^T   (1024 x 3072 x 768)
        {
            dim3 g((D2 + BN - 1) / BN, (Tt + BM - 1) / BM);
            gemm_tn<0><<<g, blk256>>>(hnb, Hd, ipw, Hd, projb, D2, Tt, D2, Hd, nullptr);
        }

        // 3. conv shift + silu -> g_hs ; writes new_conv
        conv_kernel<<<(TDN + 255) / 256, blk256>>>(csl, cw, cb, ocl);

        // 4. xdb = hs @ x_proj_w[l]^T   (1024 x 80 x 1536)
        {
            dim3 g((XDBW + BN - 1) / BN, (Tt + BM - 1) / BM);
            gemm_tn<0><<<g, blk256>>>(hsb, DIN, xpw, DIN, xdbb, XDBW, Tt, XDBW, DIN, nullptr);
        }

        // 5. dt = softplus(xdb[:, :R] @ dt_proj_w[l]^T + dt_proj_b[l])  (1024 x 1536 x 48)
        {
            dim3 g((DIN + BN - 1) / BN, (Tt + BM - 1) / BM);
            gemm_tn<1><<<g, blk256>>>(xdbb, XDBW, dpw, Rr, dtb, DIN, Tt, DIN, Rr, dpb);
        }

        // 6. SSM update -> g_y ; writes new_ssm
        ssm_kernel<<<TDN / 256, blk256>>>(ssl, Al, Dl, osl);

        // 7. x += y @ out_proj_w[l]^T   (1024 x 768 x 1536)
        {
            dim3 g((Hd + BN - 1) / BN, (Tt + BM - 1) / BM);
            gemm_tn<2><<<g, blk256>>>(yb, DIN, opw, DIN, xb, Hd, Tt, Hd, DIN, nullptr);
        }
    }

    // final rmsnorm -> out_x
    rmsnorm_kernel<<<Tt, 256>>>(xb, norm_f_w, out_x);
}

// round 2
// speedup vs baseline: 1.8803x; 1.8803x over previous
#include <cuda_runtime.h>
#include <cuda_bf16.h>
#include <cstdint>

// Problem constants
#define LNUM 2
#define Bsz 4
#define Pn  256
#define Hd  768
#define En  2
#define Nst 16
#define Kc4 4
#define DIN (En*Hd)          // 1536
#define Rr  48
#define Tt  (Bsz*Pn)         // 1024
#define D2  (2*DIN)          // 3072
#define XDBW (Rr + 2*Nst)    // 80

// Scratch (device globals; no allocation allowed)
__device__ float g_x   [Tt*Hd];
__device__ float g_hn  [Tt*Hd];
__device__ float g_proj[Tt*D2];
__device__ float g_hs  [Tt*DIN];
__device__ float g_xdb [Tt*XDBW];
__device__ float g_xdbp[4*Tt*XDBW];   // split-K partials for x_proj
__device__ float g_opart[2*Tt*Hd];    // split-K partials for out_proj
__device__ float g_dt  [Tt*DIN];
__device__ float g_y   [Tt*DIN];

// ---------------- RMSNorm ----------------
__global__ void rmsnorm_kernel(const float* __restrict__ x,
                               const float* __restrict__ w,
                               float* __restrict__ out) {
    int t = blockIdx.x;
    const float* row = x + (size_t)t * Hd;
    float s = 0.f;
    for (int i = threadIdx.x; i < Hd; i += blockDim.x) {
        float v = row[i];
        s += v * v;
    }
    __shared__ float sh[32];
    int lane = threadIdx.x & 31, wp = threadIdx.x >> 5;
    #pragma unroll
    for (int o = 16; o; o >>= 1) s += __shfl_down_sync(0xffffffffu, s, o);
    if (lane == 0) sh[wp] = s;
    __syncthreads();
    if (wp == 0) {
        float tot = (lane < (blockDim.x >> 5)) ? sh[lane] : 0.f;
        #pragma unroll
        for (int o = 16; o; o >>= 1) tot += __shfl_down_sync(0xffffffffu, tot, o);
        if (lane == 0) sh[0] = tot;
    }
    __syncthreads();
    float inv = rsqrtf(sh[0] / (float)Hd + 1e-5f);
    for (int i = threadIdx.x; i < Hd; i += blockDim.x)
        out[(size_t)t * Hd + i] = row[i] * inv * w[i];
}

// ---------------- TF32 split helpers ----------------
__device__ __forceinline__ void split_tf32(float x, uint32_t& hi, uint32_t& lo) {
    uint32_t h;
    asm("cvt.rna.tf32.f32 %0, %1;" : "=r"(h) : "f"(x));
    float d = x - __uint_as_float(h);
    uint32_t l;
    asm("cvt.rna.tf32.f32 %0, %1;" : "=r"(l) : "f"(d));
    hi = h; lo = l;
}

__device__ __forceinline__ void mma_tf32(float* c, const uint32_t* a, const uint32_t* b) {
    asm volatile("mma.sync.aligned.m16n8k8.row.col.f32.tf32.tf32.f32 "
        "{%0,%1,%2,%3}, {%4,%5,%6,%7}, {%8,%9}, {%0,%1,%2,%3};"
        : "+f"(c[0]), "+f"(c[1]), "+f"(c[2]), "+f"(c[3])
        : "r"(a[0]), "r"(a[1]), "r"(a[2]), "r"(a[3]), "r"(b[0]), "r"(b[1]));
}

// ---------------- Tensor-core GEMM: C = A(MxK) * B(NxK)^T ----------------
// 3-pass split-TF32 (fp32-grade accuracy). Block tile 128x64, BK=32, 256 thr.
// MODE 0: store   MODE 1: softplus(v + bias[col])   MODE 2: C += v
// SPLITK>1: blockIdx.z selects K-chunk; writes raw partial to C + z*M*ldc (MODE must be 0)
template<int MODE, int SPLITK>
__global__ void __launch_bounds__(256, 2)
mma_gemm(const float* __restrict__ A, int lda,
         const float* __restrict__ B, int ldb,
         float* __restrict__ C, int ldc,
         int M, int N, int K,
         const float* __restrict__ bias) {
    __shared__ float As[128][36];
    __shared__ float Bs[64][36];

    int tid = threadIdx.x;
    int warp = tid >> 5, lane = tid & 31;
    int wm = warp >> 1, wn = warp & 1;          // 4 x 2 warps
    int gid = lane >> 2, tig = lane & 3;

    int bm = blockIdx.y * 128, bn = blockIdx.x * 64;

    int kbeg = 0, kend = K;
    if (SPLITK > 1) {
        int chunk = K / SPLITK;
        kbeg = blockIdx.z * chunk;
        kend = kbeg + chunk;
        C += (size_t)blockIdx.z * M * ldc;
    }

    float acc[2][4][4];
    #pragma unroll
    for (int i = 0; i < 2; i++)
        #pragma unroll
        for (int j = 0; j < 4; j++)
            #pragma unroll
            for (int q = 0; q < 4; q++) acc[i][j][q] = 0.f;

    int lr = tid >> 3;            // 0..31
    int lc = (tid & 7) * 4;       // 0,4,...,28

    for (int k0 = kbeg; k0 < kend; k0 += 32) {
        // Load A tile (128 x 32)
        #pragma unroll
        for (int p = 0; p < 4; p++) {
            int row = lr + p * 32;
            int grow = bm + row;
            int kc = k0 + lc;
            float4 v = make_float4(0.f, 0.f, 0.f, 0.f);
            if (grow < M) {
                const float* pA = A + (size_t)grow * lda + kc;
                if (kc + 3 < kend) v = *(const float4*)pA;
                else {
                    if (kc + 0 < kend) v.x = pA[0];
                    if (kc + 1 < kend) v.y = pA[1];
                    if (kc + 2 < kend) v.z = pA[2];
                    if (kc + 3 < kend) v.w = pA[3];
                }
            }
            *(float4*)&As[row][lc] = v;
        }
        // Load B tile (64 x 32)
        #pragma unroll
        for (int p = 0; p < 2; p++) {
            int row = lr + p * 32;
            int grow = bn + row;
            int kc = k0 + lc;
            float4 v = make_float4(0.f, 0.f, 0.f, 0.f);
            if (grow < N) {
                const float* pB = B + (size_t)grow * ldb + kc;
                if (kc + 3 < kend) v = *(const float4*)pB;
                else {
                    if (kc + 0 < kend) v.x = pB[0];
                    if (kc + 1 < kend) v.y = pB[1];
                    if (kc + 2 < kend) v.z = pB[2];
                    if (kc + 3 < kend) v.w = pB[3];
                }
            }
            *(float4*)&Bs[row][lc] = v;
        }
        __syncthreads();

        #pragma unroll
        for (int ks = 0; ks < 4; ks++) {
            int kk = ks * 8;
            uint32_t ahi[2][4], alo[2][4];
            #pragma unroll
            for (int mt = 0; mt < 2; mt++) {
                int m = wm * 32 + mt * 16 + gid;
                float r0 = As[m][kk + tig];
                float r1 = As[m + 8][kk + tig];
                float r2 = As[m][kk + tig + 4];
                float r3 = As[m + 8][kk + tig + 4];
                split_tf32(r0, ahi[mt][0], alo[mt][0]);
                split_tf32(r1, ahi[mt][1], alo[mt][1]);
                split_tf32(r2, ahi[mt][2], alo[mt][2]);
                split_tf32(r3, ahi[mt][3], alo[mt][3]);
            }
            uint32_t bhi[4][2], blo[4][2];
            #pragma unroll
            for (int nt = 0; nt < 4; nt++) {
                int n = wn * 32 + nt * 8 + gid;
                float r0 = Bs[n][kk + tig];
                float r1 = Bs[n][kk + tig + 4];
                split_tf32(r0, bhi[nt][0], blo[nt][0]);
                split_tf32(r1, bhi[nt][1], blo[nt][1]);
            }
            #pragma unroll
            for (int mt = 0; mt < 2; mt++)
                #pragma unroll
                for (int nt = 0; nt < 4; nt++) {
                    mma_tf32(acc[mt][nt], ahi[mt], bhi[nt]);
                    mma_tf32(acc[mt][nt], ahi[mt], blo[nt]);
                    mma_tf32(acc[mt][nt], alo[mt], bhi[nt]);
                }
        }
        __syncthreads();
    }

    // Epilogue
    #pragma unroll
    for (int mt = 0; mt < 2; mt++) {
        #pragma unroll
        for (int nt = 0; nt < 4; nt++) {
            #pragma unroll
            for (int q = 0; q < 4; q++) {
                int row = bm + wm * 32 + mt * 16 + gid + ((q >> 1) ? 8 : 0);
                int col = bn + wn * 32 + nt * 8 + 2 * tig + (q & 1);
                if (row >= M || col >= N) continue;
                size_t o = (size_t)row * ldc + col;
                float v = acc[mt][nt][q];
                if (MODE == 0) {
                    C[o] = v;
                } else if (MODE == 1) {
                    v += bias[col];
                    C[o] = (v > 0.f) ? v + log1pf(expf(-v)) : log1pf(expf(v));
                } else {
                    C[o] += v;
                }
            }
        }
    }
}

// ---------------- split-K reductions ----------------
__global__ void reduce_xdb_kernel(float* __restrict__ out) {
    int i = blockIdx.x * blockDim.x + threadIdx.x;
    const int SZ = Tt * XDBW;
    if (i < SZ)
        out[i] = g_xdbp[i] + g_xdbp[i + SZ] + g_xdbp[i + 2 * SZ] + g_xdbp[i + 3 * SZ];
}

__global__ void reduce_addx_kernel(float* __restrict__ x) {
    int i = blockIdx.x * blockDim.x + threadIdx.x;
    const int SZ = Tt * Hd;
    if (i < SZ)
        x[i] += g_opart[i] + g_opart[i + SZ];
}

// ---------------- Conv shift + silu ----------------
__global__ void conv_kernel(const float* __restrict__ conv_states_l,
                            const float* __restrict__ conv_w_l,
                            const float* __restrict__ conv_b_l,
                            float* __restrict__ out_conv_l) {
    int idx = blockIdx.x * blockDim.x + threadIdx.x;
    if (idx >= Tt * DIN) return;
    int t = idx / DIN, d = idx - t * DIN;
    float4 cs = *(const float4*)(conv_states_l + (size_t)idx * 4);
    float hsv = g_proj[(size_t)t * D2 + d];
    float4 nc = make_float4(cs.y, cs.z, cs.w, hsv);
    *(float4*)(out_conv_l + (size_t)idx * 4) = nc;
    float4 w = *(const float4*)(conv_w_l + (size_t)d * 4);
    float s = nc.x * w.x + nc.y * w.y + nc.z * w.z + nc.w * w.w + conv_b_l[d];
    g_hs[idx] = s / (1.f + expf(-s));
}

// ---------------- SSM state update + gated output ----------------
__global__ void ssm_kernel(const float* __restrict__ ssm_l,
                           const float* __restrict__ A_log_l,
                           const float* __restrict__ D_l,
                           float* __restrict__ out_ssm_l) {
    __shared__ float Bsh[Nst], Csh[Nst];
    int idx = blockIdx.x * 256 + threadIdx.x;
    int t = idx / DIN, d = idx - t * DIN;
    if (threadIdx.x < 2 * Nst) {
        float v = g_xdb[(size_t)t * XDBW + Rr + threadIdx.x];
        if (threadIdx.x < Nst) Bsh[threadIdx.x] = v;
        else Csh[threadIdx.x - Nst] = v;
    }
    __syncthreads();
    float dtv = g_dt[idx];
    float hsv = g_hs[idx];
    const float* Ar = A_log_l + (size_t)d * Nst;
    const float* sr = ssm_l + (size_t)idx * Nst;
    float* so = out_ssm_l + (size_t)idx * Nst;
    float y = 0.f;
    #pragma unroll
    for (int n = 0; n < Nst; n++) {
        float a  = -expf(Ar[n]);
        float dA = expf(dtv * a);
        float ssv = sr[n] * dA + dtv * Bsh[n] * hsv;
        so[n] = ssv;
        y += ssv * Csh[n];
    }
    y += D_l[d] * hsv;
    float g = g_proj[(size_t)t * D2 + DIN + d];
    y *= g / (1.f + expf(-g));
    g_y[idx] = y;
}

extern "C" void kernel_launch(void* const* d_in, const int* in_sizes, int n_in,
                              void* d_out, int out_size) {
    const float* u          = (const float*)d_in[0];
    const float* conv_st    = (const float*)d_in[1];
    const float* ssm_st     = (const float*)d_in[2];
    const float* in_proj_w  = (const float*)d_in[3];
    const float* conv_w     = (const float*)d_in[4];
    const float* conv_b     = (const float*)d_in[5];
    const float* x_proj_w   = (const float*)d_in[6];
    const float* dt_proj_w  = (const float*)d_in[7];
    const float* dt_proj_b  = (const float*)d_in[8];
    const float* A_log      = (const float*)d_in[9];
    const float* D_w        = (const float*)d_in[10];
    const float* out_proj_w = (const float*)d_in[11];
    const float* norm_w     = (const float*)d_in[12];
    const float* norm_f_w   = (const float*)d_in[13];

    float* out_x    = (float*)d_out;
    float* out_conv = out_x + (size_t)Tt * Hd;
    float* out_ssm  = out_conv + (size_t)LNUM * Tt * DIN * Kc4;

    float *xb, *hnb, *projb, *hsb, *xdbb, *xdbp, *opart, *dtb, *yb;
    cudaGetSymbolAddress((void**)&xb,    g_x);
    cudaGetSymbolAddress((void**)&hnb,   g_hn);
    cudaGetSymbolAddress((void**)&projb, g_proj);
    cudaGetSymbolAddress((void**)&hsb,   g_hs);
    cudaGetSymbolAddress((void**)&xdbb,  g_xdb);
    cudaGetSymbolAddress((void**)&xdbp,  g_xdbp);
    cudaGetSymbolAddress((void**)&opart, g_opart);
    cudaGetSymbolAddress((void**)&dtb,   g_dt);
    cudaGetSymbolAddress((void**)&yb,    g_y);

    cudaMemcpyAsync(xb, u, sizeof(float) * (size_t)Tt * Hd, cudaMemcpyDeviceToDevice);

    const int TDN = Tt * DIN;
    dim3 blk256(256);

    for (int l = 0; l < LNUM; l++) {
        const float* ipw = in_proj_w + (size_t)l * D2 * Hd;
        const float* cw  = conv_w   + (size_t)l * DIN * Kc4;
        const float* cb  = conv_b   + (size_t)l * DIN;
        const float* xpw = x_proj_w + (size_t)l * XDBW * DIN;
        const float* dpw = dt_proj_w+ (size_t)l * DIN * Rr;
        const float* dpb = dt_proj_b+ (size_t)l * DIN;
        const float* Al  = A_log    + (size_t)l * DIN * Nst;
        const float* Dl  = D_w      + (size_t)l * DIN;
        const float* opw = out_proj_w + (size_t)l * Hd * DIN;
        const float* csl = conv_st  + (size_t)l * TDN * Kc4;
        const float* ssl = ssm_st   + (size_t)l * TDN * Nst;
        float* ocl = out_conv + (size_t)l * TDN * Kc4;
        float* osl = out_ssm  + (size_t)l * TDN * Nst;

        // 1. hn = rmsnorm(x)
        rmsnorm_kernel<<<Tt, 256>>>(xb, norm_w + (size_t)l * Hd, hnb);

        // 2. proj = hn @ in_proj_w^T   (1024 x 3072 x 768), 384 blocks
        mma_gemm<0,1><<<dim3(D2/64, Tt/128, 1), blk256>>>(
            hnb, Hd, ipw, Hd, projb, D2, Tt, D2, Hd, nullptr);

        // 3. conv shift + silu -> g_hs ; writes new_conv
        conv_kernel<<<(TDN + 255) / 256, blk256>>>(csl, cw, cb, ocl);

        // 4. xdb = hs @ x_proj_w^T   (1024 x 80 x 1536), split-K 4 -> 64 blocks
        mma_gemm<0,4><<<dim3(2, Tt/128, 4), blk256>>>(
            hsb, DIN, xpw, DIN, xdbp, XDBW, Tt, XDBW, DIN, nullptr);
        reduce_xdb_kernel<<<(Tt*XDBW + 255)/256, blk256>>>(xdbb);

        // 5. dt = softplus(xdb[:, :R] @ dt_proj_w^T + b)   (1024 x 1536 x 48)
        mma_gemm<1,1><<<dim3(DIN/64, Tt/128, 1), blk256>>>(
            xdbb, XDBW, dpw, Rr, dtb, DIN, Tt, DIN, Rr, dpb);

        // 6. SSM update -> g_y ; writes new_ssm
        ssm_kernel<<<TDN / 256, blk256>>>(ssl, Al, Dl, osl);

        // 7. x += y @ out_proj_w^T   (1024 x 768 x 1536), split-K 2 -> 192 blocks
        mma_gemm<0,2><<<dim3(Hd/64, Tt/128, 2), blk256>>>(
            yb, DIN, opw, DIN, opart, Hd, Tt, Hd, DIN, nullptr);
        reduce_addx_kernel<<<(Tt*Hd + 255)/256, blk256>>>(xb);
    }

    rmsnorm_kernel<<<Tt, 256>>>(xb, norm_f_w, out_x);
}

// round 3
// speedup vs baseline: 2.2319x; 1.1870x over previous
#include <cuda_runtime.h>
#include <cuda_bf16.h>
#include <cstdint>

// Problem constants
#define LNUM 2
#define Bsz 4
#define Pn  256
#define Hd  768
#define En  2
#define Nst 16
#define Kc4 4
#define DIN (En*Hd)          // 1536
#define Rr  48
#define Tt  (Bsz*Pn)         // 1024
#define D2  (2*DIN)          // 3072
#define XDBW (Rr + 2*Nst)    // 80

// Scratch (device globals; no allocation allowed)
__device__ float g_x   [Tt*Hd];
__device__ float g_hn  [Tt*Hd];
__device__ float g_proj[Tt*D2];
__device__ float g_hs  [Tt*DIN];
__device__ float g_xdb [Tt*XDBW];
__device__ float g_xdbp[4*Tt*XDBW];   // split-K partials for x_proj
__device__ float g_opart[2*Tt*Hd];    // split-K partials for out_proj
__device__ float g_dt  [Tt*DIN];
__device__ float g_y   [Tt*DIN];

// ---------------- RMSNorm ----------------
__global__ void rmsnorm_kernel(const float* __restrict__ x,
                               const float* __restrict__ w,
                               float* __restrict__ out) {
    int t = blockIdx.x;
    const float* row = x + (size_t)t * Hd;
    float s = 0.f;
    for (int i = threadIdx.x; i < Hd; i += blockDim.x) {
        float v = row[i];
        s += v * v;
    }
    __shared__ float sh[32];
    int lane = threadIdx.x & 31, wp = threadIdx.x >> 5;
    #pragma unroll
    for (int o = 16; o; o >>= 1) s += __shfl_down_sync(0xffffffffu, s, o);
    if (lane == 0) sh[wp] = s;
    __syncthreads();
    if (wp == 0) {
        float tot = (lane < (blockDim.x >> 5)) ? sh[lane] : 0.f;
        #pragma unroll
        for (int o = 16; o; o >>= 1) tot += __shfl_down_sync(0xffffffffu, tot, o);
        if (lane == 0) sh[0] = tot;
    }
    __syncthreads();
    float inv = rsqrtf(sh[0] / (float)Hd + 1e-5f);
    for (int i = threadIdx.x; i < Hd; i += blockDim.x)
        out[(size_t)t * Hd + i] = row[i] * inv * w[i];
}

// ---------------- TF32 helpers ----------------
__device__ __forceinline__ uint32_t cvt_tf32(float x) {
    uint32_t r;
    asm("cvt.rna.tf32.f32 %0, %1;" : "=r"(r) : "f"(x));
    return r;
}
__device__ __forceinline__ void split_tf32(float x, uint32_t& hi, uint32_t& lo) {
    hi = cvt_tf32(x);
    lo = cvt_tf32(x - __uint_as_float(hi));
}
__device__ __forceinline__ void mma_tf32(float* c, const uint32_t* a, const uint32_t* b) {
    asm volatile("mma.sync.aligned.m16n8k8.row.col.f32.tf32.tf32.f32 "
        "{%0,%1,%2,%3}, {%4,%5,%6,%7}, {%8,%9}, {%0,%1,%2,%3};"
        : "+f"(c[0]), "+f"(c[1]), "+f"(c[2]), "+f"(c[3])
        : "r"(a[0]), "r"(a[1]), "r"(a[2]), "r"(a[3]), "r"(b[0]), "r"(b[1]));
}

// ---------------- Pipelined tensor-core GEMM: C = A(MxK) * B(NxK)^T --------
// 3-pass split-TF32. Block tile 128x64, BK=32, 256 threads.
// Double-buffered smem, hi/lo splits precomputed at the load stage.
// MODE 0: store   MODE 1: softplus(v + bias[col])
// SPLITK>1: blockIdx.z selects K chunk; raw partial -> C + z*M*ldc (MODE 0)
#define APLANE (128*36)
#define BPLANE (64*36)
#define GEMM_SMEM_U32 (2*APLANE*2 + 2*BPLANE*2)
#define GEMM_SMEM_BYTES (GEMM_SMEM_U32*4)

template<int MODE, int SPLITK>
__global__ void __launch_bounds__(256, 1)
mma_gemm(const float* __restrict__ A, int lda,
         const float* __restrict__ B, int ldb,
         float* __restrict__ C, int ldc,
         int M, int N, int K,
         const float* __restrict__ bias) {
    extern __shared__ uint32_t smem_u32[];
    uint32_t* AsH = smem_u32;                 // [2][128][36]
    uint32_t* AsL = smem_u32 + 2*APLANE;      // [2][128][36]
    uint32_t* BsH = smem_u32 + 4*APLANE;      // [2][64][36]
    uint32_t* BsL = BsH + 2*BPLANE;           // [2][64][36]

    int tid = threadIdx.x;
    int warp = tid >> 5, lane = tid & 31;
    int wm = warp >> 1, wn = warp & 1;        // 4 x 2 warps
    int gid = lane >> 2, tig = lane & 3;

    int bm = blockIdx.y * 128, bn = blockIdx.x * 64;

    int kbeg = 0, kend = K;
    if (SPLITK > 1) {
        int chunk = K / SPLITK;
        kbeg = blockIdx.z * chunk;
        kend = kbeg + chunk;
        C += (size_t)blockIdx.z * M * ldc;
    }

    float acc[2][4][4];
    #pragma unroll
    for (int i = 0; i < 2; i++)
        #pragma unroll
        for (int j = 0; j < 4; j++)
            #pragma unroll
            for (int q = 0; q < 4; q++) acc[i][j][q] = 0.f;

    int lr = tid >> 3;            // 0..31
    int lc = (tid & 7) * 4;       // 0,4,...,28

    float4 ra[4], rb[2];

    // --- load tile (k0) into registers ---
    auto load_regs = [&](int k0) {
        #pragma unroll
        for (int p = 0; p < 4; p++) {
            int grow = bm + lr + p * 32;
            int kc = k0 + lc;
            float4 v = make_float4(0.f, 0.f, 0.f, 0.f);
            if (grow < M) {
                const float* pA = A + (size_t)grow * lda + kc;
                if (kc + 3 < kend) v = *(const float4*)pA;
                else {
                    if (kc + 0 < kend) v.x = pA[0];
                    if (kc + 1 < kend) v.y = pA[1];
                    if (kc + 2 < kend) v.z = pA[2];
                    if (kc + 3 < kend) v.w = pA[3];
                }
            }
            ra[p] = v;
        }
        #pragma unroll
        for (int p = 0; p < 2; p++) {
            int grow = bn + lr + p * 32;
            int kc = k0 + lc;
            float4 v = make_float4(0.f, 0.f, 0.f, 0.f);
            if (grow < N) {
                const float* pB = B + (size_t)grow * ldb + kc;
                if (kc + 3 < kend) v = *(const float4*)pB;
                else {
                    if (kc + 0 < kend) v.x = pB[0];
                    if (kc + 1 < kend) v.y = pB[1];
                    if (kc + 2 < kend) v.z = pB[2];
                    if (kc + 3 < kend) v.w = pB[3];
                }
            }
            rb[p] = v;
        }
    };

    // --- split registers and store into smem buffer ---
    auto store_split = [&](int buf) {
        #pragma unroll
        for (int p = 0; p < 4; p++) {
            int row = lr + p * 32;
            uint32_t h0,h1,h2,h3,l0,l1,l2,l3;
            split_tf32(ra[p].x, h0, l0);
            split_tf32(ra[p].y, h1, l1);
            split_tf32(ra[p].z, h2, l2);
            split_tf32(ra[p].w, h3, l3);
            int off = buf*APLANE + row*36 + lc;
            *(uint4*)&AsH[off] = make_uint4(h0,h1,h2,h3);
            *(uint4*)&AsL[off] = make_uint4(l0,l1,l2,l3);
        }
        #pragma unroll
        for (int p = 0; p < 2; p++) {
            int row = lr + p * 32;
            uint32_t h0,h1,h2,h3,l0,l1,l2,l3;
            split_tf32(rb[p].x, h0, l0);
            split_tf32(rb[p].y, h1, l1);
            split_tf32(rb[p].z, h2, l2);
            split_tf32(rb[p].w, h3, l3);
            int off = buf*BPLANE + row*36 + lc;
            *(uint4*)&BsH[off] = make_uint4(h0,h1,h2,h3);
            *(uint4*)&BsL[off] = make_uint4(l0,l1,l2,l3);
        }
    };

    // --- compute one K-tile (32) from smem buffer ---
    auto compute = [&](int buf) {
        #pragma unroll
        for (int ks = 0; ks < 4; ks++) {
            int kk = ks * 8;
            uint32_t ahi[2][4], alo[2][4];
            #pragma unroll
            for (int mt = 0; mt < 2; mt++) {
                int m = wm * 32 + mt * 16 + gid;
                int o = buf*APLANE + m*36 + kk + tig;
                ahi[mt][0] = AsH[o];
                ahi[mt][1] = AsH[o + 8*36];
                ahi[mt][2] = AsH[o + 4];
                ahi[mt][3] = AsH[o + 8*36 + 4];
                alo[mt][0] = AsL[o];
                alo[mt][1] = AsL[o + 8*36];
                alo[mt][2] = AsL[o + 4];
                alo[mt][3] = AsL[o + 8*36 + 4];
            }
            uint32_t bhi[4][2], blo[4][2];
            #pragma unroll
            for (int nt = 0; nt < 4; nt++) {
                int n = wn * 32 + nt * 8 + gid;
                int o = buf*BPLANE + n*36 + kk + tig;
                bhi[nt][0] = BsH[o];
                bhi[nt][1] = BsH[o + 4];
                blo[nt][0] = BsL[o];
                blo[nt][1] = BsL[o + 4];
            }
            #pragma unroll
            for (int mt = 0; mt < 2; mt++)
                #pragma unroll
                for (int nt = 0; nt < 4; nt++) {
                    mma_tf32(acc[mt][nt], ahi[mt], bhi[nt]);
                    mma_tf32(acc[mt][nt], ahi[mt], blo[nt]);
                    mma_tf32(acc[mt][nt], alo[mt], bhi[nt]);
                }
        }
    };

    int nk = (kend - kbeg + 31) >> 5;

    load_regs(kbeg);
    store_split(0);
    __syncthreads();

    for (int it = 0; it < nk; it++) {
        int cur = it & 1;
        if (it + 1 < nk) load_regs(kbeg + (it + 1) * 32);
        compute(cur);
        __syncthreads();
        if (it + 1 < nk) {
            store_split(cur ^ 1);
            __syncthreads();
        }
    }

    // Epilogue
    #pragma unroll
    for (int mt = 0; mt < 2; mt++) {
        #pragma unroll
        for (int nt = 0; nt < 4; nt++) {
            #pragma unroll
            for (int q = 0; q < 4; q++) {
                int row = bm + wm * 32 + mt * 16 + gid + ((q >> 1) ? 8 : 0);
                int col = bn + wn * 32 + nt * 8 + 2 * tig + (q & 1);
                if (row >= M || col >= N) continue;
                size_t o = (size_t)row * ldc + col;
                float v = acc[mt][nt][q];
                if (MODE == 0) {
                    C[o] = v;
                } else {
                    v += bias[col];
                    C[o] = (v > 0.f) ? v + log1pf(expf(-v)) : log1pf(expf(v));
                }
            }
        }
    }
}

// ---------------- split-K reductions ----------------
__global__ void reduce_xdb_kernel(float* __restrict__ out) {
    int i = blockIdx.x * blockDim.x + threadIdx.x;
    const int SZ = Tt * XDBW;
    if (i < SZ)
        out[i] = g_xdbp[i] + g_xdbp[i + SZ] + g_xdbp[i + 2 * SZ] + g_xdbp[i + 3 * SZ];
}

__global__ void reduce_addx_kernel(float* __restrict__ x) {
    int i = blockIdx.x * blockDim.x + threadIdx.x;
    const int SZ = Tt * Hd;
    if (i < SZ)
        x[i] += g_opart[i] + g_opart[i + SZ];
}

// ---------------- Conv shift + silu ----------------
__global__ void conv_kernel(const float* __restrict__ conv_states_l,
                            const float* __restrict__ conv_w_l,
                            const float* __restrict__ conv_b_l,
                            float* __restrict__ out_conv_l) {
    int idx = blockIdx.x * blockDim.x + threadIdx.x;
    if (idx >= Tt * DIN) return;
    int t = idx / DIN, d = idx - t * DIN;
    float4 cs = *(const float4*)(conv_states_l + (size_t)idx * 4);
    float hsv = g_proj[(size_t)t * D2 + d];
    float4 nc = make_float4(cs.y, cs.z, cs.w, hsv);
    *(float4*)(out_conv_l + (size_t)idx * 4) = nc;
    float4 w = *(const float4*)(conv_w_l + (size_t)d * 4);
    float s = nc.x * w.x + nc.y * w.y + nc.z * w.z + nc.w * w.w + conv_b_l[d];
    g_hs[idx] = s / (1.f + expf(-s));
}

// ---------------- SSM state update + gated output ----------------
__global__ void ssm_kernel(const float* __restrict__ ssm_l,
                           const float* __restrict__ A_log_l,
                           const float* __restrict__ D_l,
                           float* __restrict__ out_ssm_l) {
    __shared__ float Bsh[Nst], Csh[Nst];
    int idx = blockIdx.x * 256 + threadIdx.x;
    int t = idx / DIN, d = idx - t * DIN;
    if (threadIdx.x < 2 * Nst) {
        float v = g_xdb[(size_t)t * XDBW + Rr + threadIdx.x];
        if (threadIdx.x < Nst) Bsh[threadIdx.x] = v;
        else Csh[threadIdx.x - Nst] = v;
    }
    __syncthreads();
    float dtv = g_dt[idx];
    float hsv = g_hs[idx];
    const float* Ar = A_log_l + (size_t)d * Nst;
    const float* sr = ssm_l + (size_t)idx * Nst;
    float* so = out_ssm_l + (size_t)idx * Nst;
    float y = 0.f;
    #pragma unroll
    for (int n = 0; n < Nst; n++) {
        float a  = -expf(Ar[n]);
        float dA = expf(dtv * a);
        float ssv = sr[n] * dA + dtv * Bsh[n] * hsv;
        so[n] = ssv;
        y += ssv * Csh[n];
    }
    y += D_l[d] * hsv;
    float g = g_proj[(size_t)t * D2 + DIN + d];
    y *= g / (1.f + expf(-g));
    g_y[idx] = y;
}

extern "C" void kernel_launch(void* const* d_in, const int* in_sizes, int n_in,
                              void* d_out, int out_size) {
    const float* u          = (const float*)d_in[0];
    const float* conv_st    = (const float*)d_in[1];
    const float* ssm_st     = (const float*)d_in[2];
    const float* in_proj_w  = (const float*)d_in[3];
    const float* conv_w     = (const float*)d_in[4];
    const float* conv_b     = (const float*)d_in[5];
    const float* x_proj_w   = (const float*)d_in[6];
    const float* dt_proj_w  = (const float*)d_in[7];
    const float* dt_proj_b  = (const float*)d_in[8];
    const float* A_log      = (const float*)d_in[9];
    const float* D_w        = (const float*)d_in[10];
    const float* out_proj_w = (const float*)d_in[11];
    const float* norm_w     = (const float*)d_in[12];
    const float* norm_f_w   = (const float*)d_in[13];

    float* out_x    = (float*)d_out;
    float* out_conv = out_x + (size_t)Tt * Hd;
    float* out_ssm  = out_conv + (size_t)LNUM * Tt * DIN * Kc4;

    float *xb, *hnb, *projb, *hsb, *xdbb, *xdbp, *opart, *dtb, *yb;
    cudaGetSymbolAddress((void**)&xb,    g_x);
    cudaGetSymbolAddress((void**)&hnb,   g_hn);
    cudaGetSymbolAddress((void**)&projb, g_proj);
    cudaGetSymbolAddress((void**)&hsb,   g_hs);
    cudaGetSymbolAddress((void**)&xdbb,  g_xdb);
    cudaGetSymbolAddress((void**)&xdbp,  g_xdbp);
    cudaGetSymbolAddress((void**)&opart, g_opart);
    cudaGetSymbolAddress((void**)&dtb,   g_dt);
    cudaGetSymbolAddress((void**)&yb,    g_y);

    // raise dynamic smem limit (idempotent; first set happens on the
    // uncaptured correctness call)
    cudaFuncSetAttribute((const void*)mma_gemm<0,1>,
        cudaFuncAttributeMaxDynamicSharedMemorySize, GEMM_SMEM_BYTES);
    cudaFuncSetAttribute((const void*)mma_gemm<0,4>,
        cudaFuncAttributeMaxDynamicSharedMemorySize, GEMM_SMEM_BYTES);
    cudaFuncSetAttribute((const void*)mma_gemm<1,1>,
        cudaFuncAttributeMaxDynamicSharedMemorySize, GEMM_SMEM_BYTES);
    cudaFuncSetAttribute((const void*)mma_gemm<0,2>,
        cudaFuncAttributeMaxDynamicSharedMemorySize, GEMM_SMEM_BYTES);

    cudaMemcpyAsync(xb, u, sizeof(float) * (size_t)Tt * Hd, cudaMemcpyDeviceToDevice);

    const int TDN = Tt * DIN;
    dim3 blk256(256);

    for (int l = 0; l < LNUM; l++) {
        const float* ipw = in_proj_w + (size_t)l * D2 * Hd;
        const float* cw  = conv_w   + (size_t)l * DIN * Kc4;
        const float* cb  = conv_b   + (size_t)l * DIN;
        const float* xpw = x_proj_w + (size_t)l * XDBW * DIN;
        const float* dpw = dt_proj_w+ (size_t)l * DIN * Rr;
        const float* dpb = dt_proj_b+ (size_t)l * DIN;
        const float* Al  = A_log    + (size_t)l * DIN * Nst;
        const float* Dl  = D_w      + (size_t)l * DIN;
        const float* opw = out_proj_w + (size_t)l * Hd * DIN;
        const float* csl = conv_st  + (size_t)l * TDN * Kc4;
        const float* ssl = ssm_st   + (size_t)l * TDN * Nst;
        float* ocl = out_conv + (size_t)l * TDN * Kc4;
        float* osl = out_ssm  + (size_t)l * TDN * Nst;

        // 1. hn = rmsnorm(x)
        rmsnorm_kernel<<<Tt, 256>>>(xb, norm_w + (size_t)l * Hd, hnb);

        // 2. proj = hn @ in_proj_w^T   (1024 x 3072 x 768)
        mma_gemm<0,1><<<dim3(D2/64, Tt/128, 1), blk256, GEMM_SMEM_BYTES>>>(
            hnb, Hd, ipw, Hd, projb, D2, Tt, D2, Hd, nullptr);

        // 3. conv shift + silu -> g_hs ; writes new_conv
        conv_kernel<<<(TDN + 255) / 256, blk256>>>(csl, cw, cb, ocl);

        // 4. xdb = hs @ x_proj_w^T   (1024 x 80 x 1536), split-K 4
        mma_gemm<0,4><<<dim3(2, Tt/128, 4), blk256, GEMM_SMEM_BYTES>>>(
            hsb, DIN, xpw, DIN, xdbp, XDBW, Tt, XDBW, DIN, nullptr);
        reduce_xdb_kernel<<<(Tt*XDBW + 255)/256, blk256>>>(xdbb);

        // 5. dt = softplus(xdb[:, :R] @ dt_proj_w^T + b)   (1024 x 1536 x 48)
        mma_gemm<1,1><<<dim3(DIN/64, Tt/128, 1), blk256, GEMM_SMEM_BYTES>>>(
            xdbb, XDBW, dpw, Rr, dtb, DIN, Tt, DIN, Rr, dpb);

        // 6. SSM update -> g_y ; writes new_ssm
        ssm_kernel<<<TDN / 256, blk256>>>(ssl, Al, Dl, osl);

        // 7. x += y @ out_proj_w^T   (1024 x 768 x 1536), split-K 2
        mma_gemm<0,2><<<dim3(Hd/64, Tt/128, 2), blk256, GEMM_SMEM_BYTES>>>(
            yb, DIN, opw, DIN, opart, Hd, Tt, Hd, DIN, nullptr);
        reduce_addx_kernel<<<(Tt*Hd + 255)/256, blk256>>>(xb);
    }

    rmsnorm_kernel<<<Tt, 256>>>(xb, norm_f_w, out_x);
}

// round 4
// speedup vs baseline: 2.4117x; 1.0805x over previous
#include <cuda_runtime.h>
#include <cuda_bf16.h>
#include <cstdint>

// Problem constants
#define LNUM 2
#define Bsz 4
#define Pn  256
#define Hd  768
#define En  2
#define Nst 16
#define Kc4 4
#define DIN (En*Hd)          // 1536
#define Rr  48
#define Tt  (Bsz*Pn)         // 1024
#define D2  (2*DIN)          // 3072
#define XDBW (Rr + 2*Nst)    // 80

#define XSPLIT 8
#define OSPLIT 4

// Scratch (device globals; no allocation allowed)
__device__ float g_x   [Tt*Hd];
__device__ float g_hn  [Tt*Hd];
__device__ float g_proj[Tt*D2];
__device__ float g_hs  [Tt*DIN];
__device__ float g_xdb [Tt*XDBW];
__device__ float g_xdbp[XSPLIT*Tt*XDBW];
__device__ float g_opart[OSPLIT*Tt*Hd];
__device__ float g_dt  [Tt*DIN];
__device__ float g_y   [Tt*DIN];

// ---------------- RMSNorm ----------------
__global__ void rmsnorm_kernel(const float* __restrict__ x,
                               const float* __restrict__ w,
                               float* __restrict__ out) {
    int t = blockIdx.x;
    const float* row = x + (size_t)t * Hd;
    float s = 0.f;
    for (int i = threadIdx.x; i < Hd; i += blockDim.x) {
        float v = row[i];
        s += v * v;
    }
    __shared__ float sh[32];
    int lane = threadIdx.x & 31, wp = threadIdx.x >> 5;
    #pragma unroll
    for (int o = 16; o; o >>= 1) s += __shfl_down_sync(0xffffffffu, s, o);
    if (lane == 0) sh[wp] = s;
    __syncthreads();
    if (wp == 0) {
        float tot = (lane < (blockDim.x >> 5)) ? sh[lane] : 0.f;
        #pragma unroll
        for (int o = 16; o; o >>= 1) tot += __shfl_down_sync(0xffffffffu, tot, o);
        if (lane == 0) sh[0] = tot;
    }
    __syncthreads();
    float inv = rsqrtf(sh[0] / (float)Hd + 1e-5f);
    for (int i = threadIdx.x; i < Hd; i += blockDim.x)
        out[(size_t)t * Hd + i] = row[i] * inv * w[i];
}

// ---------------- TF32 helpers ----------------
__device__ __forceinline__ uint32_t cvt_tf32(float x) {
    uint32_t r;
    asm("cvt.rna.tf32.f32 %0, %1;" : "=r"(r) : "f"(x));
    return r;
}
__device__ __forceinline__ void split_tf32(float x, uint32_t& hi, uint32_t& lo) {
    hi = cvt_tf32(x);
    lo = cvt_tf32(x - __uint_as_float(hi));
}
__device__ __forceinline__ void mma_tf32(float* c, const uint32_t* a, const uint32_t* b) {
    asm volatile("mma.sync.aligned.m16n8k8.row.col.f32.tf32.tf32.f32 "
        "{%0,%1,%2,%3}, {%4,%5,%6,%7}, {%8,%9}, {%0,%1,%2,%3};"
        : "+f"(c[0]), "+f"(c[1]), "+f"(c[2]), "+f"(c[3])
        : "r"(a[0]), "r"(a[1]), "r"(a[2]), "r"(a[3]), "r"(b[0]), "r"(b[1]));
}

// ---------------- Pipelined tensor-core GEMM: C = A(MxK) * B(NxK)^T --------
// 3-pass split-TF32 (fp32-grade). Block tile 128x64, BK=32, 512 threads,
// warp grid 4x4, per-warp tile 32x16. Double-buffered smem, hi/lo splits
// precomputed at load stage, ONE barrier per K-tile.
// MODE 0: store   MODE 1: softplus(v + bias[col])
// SPLITK>1: blockIdx.z selects K chunk; raw partial -> C + z*M*ldc (MODE 0)
#define APLANE (128*36)
#define BPLANE (64*36)
#define GEMM_SMEM_U32 (2*APLANE*2 + 2*BPLANE*2)
#define GEMM_SMEM_BYTES (GEMM_SMEM_U32*4)

template<int MODE, int SPLITK>
__global__ void __launch_bounds__(512, 1)
mma_gemm(const float* __restrict__ A, int lda,
         const float* __restrict__ B, int ldb,
         float* __restrict__ C, int ldc,
         int M, int N, int K,
         const float* __restrict__ bias) {
    extern __shared__ uint32_t smem_u32[];
    uint32_t* AsH = smem_u32;                 // [2][128][36]
    uint32_t* AsL = smem_u32 + 2*APLANE;
    uint32_t* BsH = smem_u32 + 4*APLANE;      // [2][64][36]
    uint32_t* BsL = BsH + 2*BPLANE;

    int tid = threadIdx.x;
    int warp = tid >> 5, lane = tid & 31;
    int wm = warp >> 2, wn = warp & 3;        // 4 x 4 warps
    int gid = lane >> 2, tig = lane & 3;

    int bm = blockIdx.y * 128, bn = blockIdx.x * 64;

    int kbeg = 0, kend = K;
    if (SPLITK > 1) {
        int chunk = K / SPLITK;
        kbeg = blockIdx.z * chunk;
        kend = kbeg + chunk;
        C += (size_t)blockIdx.z * M * ldc;
    }

    float acc[2][2][4];
    #pragma unroll
    for (int i = 0; i < 2; i++)
        #pragma unroll
        for (int j = 0; j < 2; j++)
            #pragma unroll
            for (int q = 0; q < 4; q++) acc[i][j][q] = 0.f;

    int lr = tid >> 3;            // 0..63
    int lc = (tid & 7) * 4;       // 0,4,...,28

    float4 ra[2], rb;

    auto load_regs = [&](int k0) {
        #pragma unroll
        for (int p = 0; p < 2; p++) {
            int grow = bm + lr + p * 64;
            int kc = k0 + lc;
            float4 v = make_float4(0.f, 0.f, 0.f, 0.f);
            if (grow < M) {
                const float* pA = A + (size_t)grow * lda + kc;
                if (kc + 3 < kend) v = *(const float4*)pA;
                else {
                    if (kc + 0 < kend) v.x = pA[0];
                    if (kc + 1 < kend) v.y = pA[1];
                    if (kc + 2 < kend) v.z = pA[2];
                    if (kc + 3 < kend) v.w = pA[3];
                }
            }
            ra[p] = v;
        }
        {
            int grow = bn + lr;
            int kc = k0 + lc;
            float4 v = make_float4(0.f, 0.f, 0.f, 0.f);
            if (grow < N) {
                const float* pB = B + (size_t)grow * ldb + kc;
                if (kc + 3 < kend) v = *(const float4*)pB;
                else {
                    if (kc + 0 < kend) v.x = pB[0];
                    if (kc + 1 < kend) v.y = pB[1];
                    if (kc + 2 < kend) v.z = pB[2];
                    if (kc + 3 < kend) v.w = pB[3];
                }
            }
            rb = v;
        }
    };

    auto store_split = [&](int buf) {
        #pragma unroll
        for (int p = 0; p < 2; p++) {
            int row = lr + p * 64;
            uint32_t h0,h1,h2,h3,l0,l1,l2,l3;
            split_tf32(ra[p].x, h0, l0);
            split_tf32(ra[p].y, h1, l1);
            split_tf32(ra[p].z, h2, l2);
            split_tf32(ra[p].w, h3, l3);
            int off = buf*APLANE + row*36 + lc;
            *(uint4*)&AsH[off] = make_uint4(h0,h1,h2,h3);
            *(uint4*)&AsL[off] = make_uint4(l0,l1,l2,l3);
        }
        {
            uint32_t h0,h1,h2,h3,l0,l1,l2,l3;
            split_tf32(rb.x, h0, l0);
            split_tf32(rb.y, h1, l1);
            split_tf32(rb.z, h2, l2);
            split_tf32(rb.w, h3, l3);
            int off = buf*BPLANE + lr*36 + lc;
            *(uint4*)&BsH[off] = make_uint4(h0,h1,h2,h3);
            *(uint4*)&BsL[off] = make_uint4(l0,l1,l2,l3);
        }
    };

    auto compute = [&](int buf) {
        #pragma unroll
        for (int ks = 0; ks < 4; ks++) {
            int kk = ks * 8;
            uint32_t ahi[2][4], alo[2][4];
            #pragma unroll
            for (int mt = 0; mt < 2; mt++) {
                int m = wm * 32 + mt * 16 + gid;
                int o = buf*APLANE + m*36 + kk + tig;
                ahi[mt][0] = AsH[o];
                ahi[mt][1] = AsH[o + 8*36];
                ahi[mt][2] = AsH[o + 4];
                ahi[mt][3] = AsH[o + 8*36 + 4];
                alo[mt][0] = AsL[o];
                alo[mt][1] = AsL[o + 8*36];
                alo[mt][2] = AsL[o + 4];
                alo[mt][3] = AsL[o + 8*36 + 4];
            }
            uint32_t bhi[2][2], blo[2][2];
            #pragma unroll
            for (int nt = 0; nt < 2; nt++) {
                int n = wn * 16 + nt * 8 + gid;
                int o = buf*BPLANE + n*36 + kk + tig;
                bhi[nt][0] = BsH[o];
                bhi[nt][1] = BsH[o + 4];
                blo[nt][0] = BsL[o];
                blo[nt][1] = BsL[o + 4];
            }
            #pragma unroll
            for (int mt = 0; mt < 2; mt++)
                #pragma unroll
                for (int nt = 0; nt < 2; nt++) {
                    mma_tf32(acc[mt][nt], ahi[mt], bhi[nt]);
                    mma_tf32(acc[mt][nt], ahi[mt], blo[nt]);
                    mma_tf32(acc[mt][nt], alo[mt], bhi[nt]);
                }
        }
    };

    int nk = (kend - kbeg + 31) >> 5;

    load_regs(kbeg);
    store_split(0);

    for (int it = 0; it < nk; it++) {
        int cur = it & 1;
        if (it + 1 < nk) load_regs(kbeg + (it + 1) * 32);
        __syncthreads();
        compute(cur);
        if (it + 1 < nk) store_split(cur ^ 1);
    }

    // Epilogue
    #pragma unroll
    for (int mt = 0; mt < 2; mt++) {
        #pragma unroll
        for (int nt = 0; nt < 2; nt++) {
            #pragma unroll
            for (int q = 0; q < 4; q++) {
                int row = bm + wm * 32 + mt * 16 + gid + ((q >> 1) ? 8 : 0);
                int col = bn + wn * 16 + nt * 8 + 2 * tig + (q & 1);
                if (row >= M || col >= N) continue;
                size_t o = (size_t)row * ldc + col;
                float v = acc[mt][nt][q];
                if (MODE == 0) {
                    C[o] = v;
                } else {
                    v += bias[col];
                    C[o] = (v > 0.f) ? v + log1pf(expf(-v)) : log1pf(expf(v));
                }
            }
        }
    }
}

// ---------------- split-K reductions ----------------
__global__ void reduce_xdb_kernel(float* __restrict__ out) {
    int i = blockIdx.x * blockDim.x + threadIdx.x;
    const int SZ = Tt * XDBW;
    if (i < SZ) {
        float s = 0.f;
        #pragma unroll
        for (int p = 0; p < XSPLIT; p++) s += g_xdbp[i + p * SZ];
        out[i] = s;
    }
}

__global__ void reduce_addx_kernel(float* __restrict__ x) {
    int i = blockIdx.x * blockDim.x + threadIdx.x;
    const int SZ = Tt * Hd;
    if (i < SZ) {
        float s = x[i];
        #pragma unroll
        for (int p = 0; p < OSPLIT; p++) s += g_opart[i + p * SZ];
        x[i] = s;
    }
}

// ---------------- Conv shift + silu ----------------
__global__ void conv_kernel(const float* __restrict__ conv_states_l,
                            const float* __restrict__ conv_w_l,
                            const float* __restrict__ conv_b_l,
                            float* __restrict__ out_conv_l) {
    int idx = blockIdx.x * blockDim.x + threadIdx.x;
    if (idx >= Tt * DIN) return;
    int t = idx / DIN, d = idx - t * DIN;
    float4 cs = *(const float4*)(conv_states_l + (size_t)idx * 4);
    float hsv = g_proj[(size_t)t * D2 + d];
    float4 nc = make_float4(cs.y, cs.z, cs.w, hsv);
    *(float4*)(out_conv_l + (size_t)idx * 4) = nc;
    float4 w = *(const float4*)(conv_w_l + (size_t)d * 4);
    float s = nc.x * w.x + nc.y * w.y + nc.z * w.z + nc.w * w.w + conv_b_l[d];
    g_hs[idx] = s / (1.f + expf(-s));
}

// ---------------- SSM state update + gated output ----------------
__global__ void ssm_kernel(const float* __restrict__ ssm_l,
                           const float* __restrict__ A_log_l,
                           const float* __restrict__ D_l,
                           float* __restrict__ out_ssm_l) {
    __shared__ float Bsh[Nst], Csh[Nst];
    int idx = blockIdx.x * 256 + threadIdx.x;
    int t = idx / DIN, d = idx - t * DIN;
    if (threadIdx.x < 2 * Nst) {
        float v = g_xdb[(size_t)t * XDBW + Rr + threadIdx.x];
        if (threadIdx.x < Nst) Bsh[threadIdx.x] = v;
        else Csh[threadIdx.x - Nst] = v;
    }
    __syncthreads();
    float dtv = g_dt[idx];
    float hsv = g_hs[idx];
    const float* Ar = A_log_l + (size_t)d * Nst;
    const float* sr = ssm_l + (size_t)idx * Nst;
    float* so = out_ssm_l + (size_t)idx * Nst;
    float y = 0.f;
    #pragma unroll
    for (int n = 0; n < Nst; n++) {
        float a  = -expf(Ar[n]);
        float dA = expf(dtv * a);
        float ssv = sr[n] * dA + dtv * Bsh[n] * hsv;
        so[n] = ssv;
        y += ssv * Csh[n];
    }
    y += D_l[d] * hsv;
    float g = g_proj[(size_t)t * D2 + DIN + d];
    y *= g / (1.f + expf(-g));
    g_y[idx] = y;
}

extern "C" void kernel_launch(void* const* d_in, const int* in_sizes, int n_in,
                              void* d_out, int out_size) {
    const float* u          = (const float*)d_in[0];
    const float* conv_st    = (const float*)d_in[1];
    const float* ssm_st     = (const float*)d_in[2];
    const float* in_proj_w  = (const float*)d_in[3];
    const float* conv_w     = (const float*)d_in[4];
    const float* conv_b     = (const float*)d_in[5];
    const float* x_proj_w   = (const float*)d_in[6];
    const float* dt_proj_w  = (const float*)d_in[7];
    const float* dt_proj_b  = (const float*)d_in[8];
    const float* A_log      = (const float*)d_in[9];
    const float* D_w        = (const float*)d_in[10];
    const float* out_proj_w = (const float*)d_in[11];
    const float* norm_w     = (const float*)d_in[12];
    const float* norm_f_w   = (const float*)d_in[13];

    float* out_x    = (float*)d_out;
    float* out_conv = out_x + (size_t)Tt * Hd;
    float* out_ssm  = out_conv + (size_t)LNUM * Tt * DIN * Kc4;

    float *xb, *hnb, *projb, *hsb, *xdbb, *xdbp, *opart, *dtb, *yb;
    cudaGetSymbolAddress((void**)&xb,    g_x);
    cudaGetSymbolAddress((void**)&hnb,   g_hn);
    cudaGetSymbolAddress((void**)&projb, g_proj);
    cudaGetSymbolAddress((void**)&hsb,   g_hs);
    cudaGetSymbolAddress((void**)&xdbb,  g_xdb);
    cudaGetSymbolAddress((void**)&xdbp,  g_xdbp);
    cudaGetSymbolAddress((void**)&opart, g_opart);
    cudaGetSymbolAddress((void**)&dtb,   g_dt);
    cudaGetSymbolAddress((void**)&yb,    g_y);

    cudaFuncSetAttribute((const void*)mma_gemm<0,1>,
        cudaFuncAttributeMaxDynamicSharedMemorySize, GEMM_SMEM_BYTES);
    cudaFuncSetAttribute((const void*)mma_gemm<0,XSPLIT>,
        cudaFuncAttributeMaxDynamicSharedMemorySize, GEMM_SMEM_BYTES);
    cudaFuncSetAttribute((const void*)mma_gemm<1,1>,
        cudaFuncAttributeMaxDynamicSharedMemorySize, GEMM_SMEM_BYTES);
    cudaFuncSetAttribute((const void*)mma_gemm<0,OSPLIT>,
        cudaFuncAttributeMaxDynamicSharedMemorySize, GEMM_SMEM_BYTES);

    cudaMemcpyAsync(xb, u, sizeof(float) * (size_t)Tt * Hd, cudaMemcpyDeviceToDevice);

    const int TDN = Tt * DIN;
    dim3 blk256(256);
    dim3 blk512(512);

    for (int l = 0; l < LNUM; l++) {
        const float* ipw = in_proj_w + (size_t)l * D2 * Hd;
        const float* cw  = conv_w   + (size_t)l * DIN * Kc4;
        const float* cb  = conv_b   + (size_t)l * DIN;
        const float* xpw = x_proj_w + (size_t)l * XDBW * DIN;
        const float* dpw = dt_proj_w+ (size_t)l * DIN * Rr;
        const float* dpb = dt_proj_b+ (size_t)l * DIN;
        const float* Al  = A_log    + (size_t)l * DIN * Nst;
        const float* Dl  = D_w      + (size_t)l * DIN;
        const float* opw = out_proj_w + (size_t)l * Hd * DIN;
        const float* csl = conv_st  + (size_t)l * TDN * Kc4;
        const float* ssl = ssm_st   + (size_t)l * TDN * Nst;
        float* ocl = out_conv + (size_t)l * TDN * Kc4;
        float* osl = out_ssm  + (size_t)l * TDN * Nst;

        // 1. hn = rmsnorm(x)
        rmsnorm_kernel<<<Tt, 256>>>(xb, norm_w + (size_t)l * Hd, hnb);

        // 2. proj = hn @ in_proj_w^T   (1024 x 3072 x 768), 384 blocks
        mma_gemm<0,1><<<dim3(D2/64, Tt/128, 1), blk512, GEMM_SMEM_BYTES>>>(
            hnb, Hd, ipw, Hd, projb, D2, Tt, D2, Hd, nullptr);

        // 3. conv shift + silu -> g_hs ; writes new_conv
        conv_kernel<<<(TDN + 255) / 256, blk256>>>(csl, cw, cb, ocl);

        // 4. xdb = hs @ x_proj_w^T   (1024 x 80 x 1536), split-K 8 -> 128 blocks
        mma_gemm<0,XSPLIT><<<dim3(2, Tt/128, XSPLIT), blk512, GEMM_SMEM_BYTES>>>(
            hsb, DIN, xpw, DIN, xdbp, XDBW, Tt, XDBW, DIN, nullptr);
        reduce_xdb_kernel<<<(Tt*XDBW + 255)/256, blk256>>>(xdbb);

        // 5. dt = softplus(xdb[:, :R] @ dt_proj_w^T + b)   (1024 x 1536 x 48)
        mma_gemm<1,1><<<dim3(DIN/64, Tt/128, 1), blk512, GEMM_SMEM_BYTES>>>(
            xdbb, XDBW, dpw, Rr, dtb, DIN, Tt, DIN, Rr, dpb);

        // 6. SSM update -> g_y ; writes new_ssm
        ssm_kernel<<<TDN / 256, blk256>>>(ssl, Al, Dl, osl);

        // 7. x += y @ out_proj_w^T   (1024 x 768 x 1536), split-K 4 -> 384 blocks
        mma_gemm<0,OSPLIT><<<dim3(Hd/64, Tt/128, OSPLIT), blk512, GEMM_SMEM_BYTES>>>(
            yb, DIN, opw, DIN, opart, Hd, Tt, Hd, DIN, nullptr);
        reduce_addx_kernel<<<(Tt*Hd + 255)/256, blk256>>>(xb);
    }

    rmsnorm_kernel<<<Tt, 256>>>(xb, norm_f_w, out_x);
}

// round 5
// speedup vs baseline: 2.9104x; 1.2068x over previous
#include <cuda_runtime.h>
#include <cuda_bf16.h>
#include <cstdint>

// Problem constants
#define LNUM 2
#define Bsz 4
#define Pn  256
#define Hd  768
#define En  2
#define Nst 16
#define Kc4 4
#define DIN (En*Hd)          // 1536
#define Rr  48
#define Tt  (Bsz*Pn)         // 1024
#define D2  (2*DIN)          // 3072
#define XDBW (Rr + 2*Nst)    // 80

#define XSPLIT 8
#define OSPLIT 4

// Scratch (device globals; no allocation allowed)
__device__ float g_x   [Tt*Hd];
__device__ float g_hn  [Tt*Hd];
__device__ float g_proj[Tt*D2];
__device__ float g_hs  [Tt*DIN];
__device__ float g_xdb [Tt*XDBW];
__device__ float g_xdbp[XSPLIT*Tt*XDBW];
__device__ float g_opart[OSPLIT*Tt*Hd];
__device__ float g_dt  [Tt*DIN];
__device__ float g_y   [Tt*DIN];

// ---------------- RMSNorm ----------------
__global__ void rmsnorm_kernel(const float* __restrict__ x,
                               const float* __restrict__ w,
                               float* __restrict__ out) {
    int t = blockIdx.x;
    const float* row = x + (size_t)t * Hd;
    float s = 0.f;
    for (int i = threadIdx.x; i < Hd; i += blockDim.x) {
        float v = row[i];
        s += v * v;
    }
    __shared__ float sh[32];
    int lane = threadIdx.x & 31, wp = threadIdx.x >> 5;
    #pragma unroll
    for (int o = 16; o; o >>= 1) s += __shfl_down_sync(0xffffffffu, s, o);
    if (lane == 0) sh[wp] = s;
    __syncthreads();
    if (wp == 0) {
        float tot = (lane < (blockDim.x >> 5)) ? sh[lane] : 0.f;
        #pragma unroll
        for (int o = 16; o; o >>= 1) tot += __shfl_down_sync(0xffffffffu, tot, o);
        if (lane == 0) sh[0] = tot;
    }
    __syncthreads();
    float inv = rsqrtf(sh[0] / (float)Hd + 1e-5f);
    for (int i = threadIdx.x; i < Hd; i += blockDim.x)
        out[(size_t)t * Hd + i] = row[i] * inv * w[i];
}

// ---------------- TF32 helpers ----------------
__device__ __forceinline__ uint32_t cvt_tf32(float x) {
    uint32_t r;
    asm("cvt.rna.tf32.f32 %0, %1;" : "=r"(r) : "f"(x));
    return r;
}
__device__ __forceinline__ void split_tf32(float x, uint32_t& hi, uint32_t& lo) {
    hi = cvt_tf32(x);
    lo = cvt_tf32(x - __uint_as_float(hi));
}
__device__ __forceinline__ void mma_tf32(float* c, const uint32_t* a, const uint32_t* b) {
    asm volatile("mma.sync.aligned.m16n8k8.row.col.f32.tf32.tf32.f32 "
        "{%0,%1,%2,%3}, {%4,%5,%6,%7}, {%8,%9}, {%0,%1,%2,%3};"
        : "+f"(c[0]), "+f"(c[1]), "+f"(c[2]), "+f"(c[3])
        : "r"(a[0]), "r"(a[1]), "r"(a[2]), "r"(a[3]), "r"(b[0]), "r"(b[1]));
}

// ---------------- Pipelined tensor-core GEMM: C = A(MxK) * B(NxK)^T --------
// 2-pass asymmetric split: A = hi+lo (exact), B truncated to TF32 once.
// C = A_hi*B_t + A_lo*B_t. Block tile 128x64, BK=32, 256 threads,
// warp grid 4x2, warp tile 32x32. Double-buffered smem (90KB -> 2 CTAs/SM).
// MODE 0: store   MODE 1: softplus(v + bias[col])
// SPLITK>1: blockIdx.z selects K chunk; raw partial -> C + z*M*ldc (MODE 0)
#define APLANE (128*36)
#define BPLANE (64*36)
#define GEMM_SMEM_U32 (2*APLANE*2 + 2*BPLANE)
#define GEMM_SMEM_BYTES (GEMM_SMEM_U32*4)

template<int MODE, int SPLITK>
__global__ void __launch_bounds__(256, 2)
mma_gemm(const float* __restrict__ A, int lda,
         const float* __restrict__ B, int ldb,
         float* __restrict__ C, int ldc,
         int M, int N, int K,
         const float* __restrict__ bias) {
    extern __shared__ uint32_t smem_u32[];
    uint32_t* AsH = smem_u32;                 // [2][128][36]
    uint32_t* AsL = smem_u32 + 2*APLANE;      // [2][128][36]
    uint32_t* BsT = smem_u32 + 4*APLANE;      // [2][64][36]

    int tid = threadIdx.x;
    int warp = tid >> 5, lane = tid & 31;
    int wm = warp >> 1, wn = warp & 1;        // 4 x 2 warps, warp tile 32x32
    int gid = lane >> 2, tig = lane & 3;

    int bm = blockIdx.y * 128, bn = blockIdx.x * 64;

    int kbeg = 0, kend = K;
    if (SPLITK > 1) {
        int chunk = K / SPLITK;
        kbeg = blockIdx.z * chunk;
        kend = kbeg + chunk;
        C += (size_t)blockIdx.z * M * ldc;
    }

    float acc[2][4][4];
    #pragma unroll
    for (int i = 0; i < 2; i++)
        #pragma unroll
        for (int j = 0; j < 4; j++)
            #pragma unroll
            for (int q = 0; q < 4; q++) acc[i][j][q] = 0.f;

    int lr = tid >> 3;            // 0..31
    int lc = (tid & 7) * 4;       // 0,4,...,28

    float4 ra[4], rb[2];

    auto load_regs = [&](int k0) {
        #pragma unroll
        for (int p = 0; p < 4; p++) {
            int grow = bm + lr + p * 32;
            int kc = k0 + lc;
            float4 v = make_float4(0.f, 0.f, 0.f, 0.f);
            if (grow < M) {
                const float* pA = A + (size_t)grow * lda + kc;
                if (kc + 3 < kend) v = *(const float4*)pA;
                else {
                    if (kc + 0 < kend) v.x = pA[0];
                    if (kc + 1 < kend) v.y = pA[1];
                    if (kc + 2 < kend) v.z = pA[2];
                    if (kc + 3 < kend) v.w = pA[3];
                }
            }
            ra[p] = v;
        }
        #pragma unroll
        for (int p = 0; p < 2; p++) {
            int grow = bn + lr + p * 32;
            int kc = k0 + lc;
            float4 v = make_float4(0.f, 0.f, 0.f, 0.f);
            if (grow < N) {
                const float* pB = B + (size_t)grow * ldb + kc;
                if (kc + 3 < kend) v = *(const float4*)pB;
                else {
                    if (kc + 0 < kend) v.x = pB[0];
                    if (kc + 1 < kend) v.y = pB[1];
                    if (kc + 2 < kend) v.z = pB[2];
                    if (kc + 3 < kend) v.w = pB[3];
                }
            }
            rb[p] = v;
        }
    };

    auto store_split = [&](int buf) {
        #pragma unroll
        for (int p = 0; p < 4; p++) {
            int row = lr + p * 32;
            uint32_t h0,h1,h2,h3,l0,l1,l2,l3;
            split_tf32(ra[p].x, h0, l0);
            split_tf32(ra[p].y, h1, l1);
            split_tf32(ra[p].z, h2, l2);
            split_tf32(ra[p].w, h3, l3);
            int off = buf*APLANE + row*36 + lc;
            *(uint4*)&AsH[off] = make_uint4(h0,h1,h2,h3);
            *(uint4*)&AsL[off] = make_uint4(l0,l1,l2,l3);
        }
        #pragma unroll
        for (int p = 0; p < 2; p++) {
            int row = lr + p * 32;
            uint32_t h0 = cvt_tf32(rb[p].x);
            uint32_t h1 = cvt_tf32(rb[p].y);
            uint32_t h2 = cvt_tf32(rb[p].z);
            uint32_t h3 = cvt_tf32(rb[p].w);
            int off = buf*BPLANE + row*36 + lc;
            *(uint4*)&BsT[off] = make_uint4(h0,h1,h2,h3);
        }
    };

    auto compute = [&](int buf) {
        #pragma unroll
        for (int ks = 0; ks < 4; ks++) {
            int kk = ks * 8;
            uint32_t ahi[2][4], alo[2][4];
            #pragma unroll
            for (int mt = 0; mt < 2; mt++) {
                int m = wm * 32 + mt * 16 + gid;
                int o = buf*APLANE + m*36 + kk + tig;
                ahi[mt][0] = AsH[o];
                ahi[mt][1] = AsH[o + 8*36];
                ahi[mt][2] = AsH[o + 4];
                ahi[mt][3] = AsH[o + 8*36 + 4];
                alo[mt][0] = AsL[o];
                alo[mt][1] = AsL[o + 8*36];
                alo[mt][2] = AsL[o + 4];
                alo[mt][3] = AsL[o + 8*36 + 4];
            }
            uint32_t bt[4][2];
            #pragma unroll
            for (int nt = 0; nt < 4; nt++) {
                int n = wn * 32 + nt * 8 + gid;
                int o = buf*BPLANE + n*36 + kk + tig;
                bt[nt][0] = BsT[o];
                bt[nt][1] = BsT[o + 4];
            }
            #pragma unroll
            for (int mt = 0; mt < 2; mt++)
                #pragma unroll
                for (int nt = 0; nt < 4; nt++) {
                    mma_tf32(acc[mt][nt], ahi[mt], bt[nt]);
                    mma_tf32(acc[mt][nt], alo[mt], bt[nt]);
                }
        }
    };

    int nk = (kend - kbeg + 31) >> 5;

    load_regs(kbeg);
    store_split(0);

    for (int it = 0; it < nk; it++) {
        int cur = it & 1;
        if (it + 1 < nk) load_regs(kbeg + (it + 1) * 32);
        __syncthreads();
        compute(cur);
        if (it + 1 < nk) store_split(cur ^ 1);
    }

    // Epilogue
    #pragma unroll
    for (int mt = 0; mt < 2; mt++) {
        #pragma unroll
        for (int nt = 0; nt < 4; nt++) {
            #pragma unroll
            for (int q = 0; q < 4; q++) {
                int row = bm + wm * 32 + mt * 16 + gid + ((q >> 1) ? 8 : 0);
                int col = bn + wn * 32 + nt * 8 + 2 * tig + (q & 1);
                if (row >= M || col >= N) continue;
                size_t o = (size_t)row * ldc + col;
                float v = acc[mt][nt][q];
                if (MODE == 0) {
                    C[o] = v;
                } else {
                    v += bias[col];
                    C[o] = (v > 0.f) ? v + log1pf(expf(-v)) : log1pf(expf(v));
                }
            }
        }
    }
}

// ---------------- split-K reductions ----------------
__global__ void reduce_xdb_kernel(float* __restrict__ out) {
    int i = blockIdx.x * blockDim.x + threadIdx.x;
    const int SZ = Tt * XDBW;
    if (i < SZ) {
        float s = 0.f;
        #pragma unroll
        for (int p = 0; p < XSPLIT; p++) s += g_xdbp[i + p * SZ];
        out[i] = s;
    }
}

__global__ void reduce_addx_kernel(float* __restrict__ x) {
    int i = blockIdx.x * blockDim.x + threadIdx.x;
    const int SZ = Tt * Hd;
    if (i < SZ) {
        float s = x[i];
        #pragma unroll
        for (int p = 0; p < OSPLIT; p++) s += g_opart[i + p * SZ];
        x[i] = s;
    }
}

// ---------------- Conv shift + silu ----------------
__global__ void conv_kernel(const float* __restrict__ conv_states_l,
                            const float* __restrict__ conv_w_l,
                            const float* __restrict__ conv_b_l,
                            float* __restrict__ out_conv_l) {
    int idx = blockIdx.x * blockDim.x + threadIdx.x;
    if (idx >= Tt * DIN) return;
    int t = idx / DIN, d = idx - t * DIN;
    float4 cs = *(const float4*)(conv_states_l + (size_t)idx * 4);
    float hsv = g_proj[(size_t)t * D2 + d];
    float4 nc = make_float4(cs.y, cs.z, cs.w, hsv);
    *(float4*)(out_conv_l + (size_t)idx * 4) = nc;
    float4 w = *(const float4*)(conv_w_l + (size_t)d * 4);
    float s = nc.x * w.x + nc.y * w.y + nc.z * w.z + nc.w * w.w + conv_b_l[d];
    g_hs[idx] = s / (1.f + expf(-s));
}

// ---------------- SSM state update + gated output ----------------
__global__ void ssm_kernel(const float* __restrict__ ssm_l,
                           const float* __restrict__ A_log_l,
                           const float* __restrict__ D_l,
                           float* __restrict__ out_ssm_l) {
    __shared__ float Bsh[Nst], Csh[Nst];
    int idx = blockIdx.x * 256 + threadIdx.x;
    int t = idx / DIN, d = idx - t * DIN;
    if (threadIdx.x < 2 * Nst) {
        float v = g_xdb[(size_t)t * XDBW + Rr + threadIdx.x];
        if (threadIdx.x < Nst) Bsh[threadIdx.x] = v;
        else Csh[threadIdx.x - Nst] = v;
    }
    __syncthreads();
    float dtv = g_dt[idx];
    float hsv = g_hs[idx];
    const float* Ar = A_log_l + (size_t)d * Nst;
    const float* sr = ssm_l + (size_t)idx * Nst;
    float* so = out_ssm_l + (size_t)idx * Nst;
    float y = 0.f;
    #pragma unroll
    for (int n = 0; n < Nst; n++) {
        float a  = -expf(Ar[n]);
        float dA = expf(dtv * a);
        float ssv = sr[n] * dA + dtv * Bsh[n] * hsv;
        so[n] = ssv;
        y += ssv * Csh[n];
    }
    y += D_l[d] * hsv;
    float g = g_proj[(size_t)t * D2 + DIN + d];
    y *= g / (1.f + expf(-g));
    g_y[idx] = y;
}

extern "C" void kernel_launch(void* const* d_in, const int* in_sizes, int n_in,
                              void* d_out, int out_size) {
    const float* u          = (const float*)d_in[0];
    const float* conv_st    = (const float*)d_in[1];
    const float* ssm_st     = (const float*)d_in[2];
    const float* in_proj_w  = (const float*)d_in[3];
    const float* conv_w     = (const float*)d_in[4];
    const float* conv_b     = (const float*)d_in[5];
    const float* x_proj_w   = (const float*)d_in[6];
    const float* dt_proj_w  = (const float*)d_in[7];
    const float* dt_proj_b  = (const float*)d_in[8];
    const float* A_log      = (const float*)d_in[9];
    const float* D_w        = (const float*)d_in[10];
    const float* out_proj_w = (const float*)d_in[11];
    const float* norm_w     = (const float*)d_in[12];
    const float* norm_f_w   = (const float*)d_in[13];

    float* out_x    = (float*)d_out;
    float* out_conv = out_x + (size_t)Tt * Hd;
    float* out_ssm  = out_conv + (size_t)LNUM * Tt * DIN * Kc4;

    float *xb, *hnb, *projb, *hsb, *xdbb, *xdbp, *opart, *dtb, *yb;
    cudaGetSymbolAddress((void**)&xb,    g_x);
    cudaGetSymbolAddress((void**)&hnb,   g_hn);
    cudaGetSymbolAddress((void**)&projb, g_proj);
    cudaGetSymbolAddress((void**)&hsb,   g_hs);
    cudaGetSymbolAddress((void**)&xdbb,  g_xdb);
    cudaGetSymbolAddress((void**)&xdbp,  g_xdbp);
    cudaGetSymbolAddress((void**)&opart, g_opart);
    cudaGetSymbolAddress((void**)&dtb,   g_dt);
    cudaGetSymbolAddress((void**)&yb,    g_y);

    cudaFuncSetAttribute((const void*)mma_gemm<0,1>,
        cudaFuncAttributeMaxDynamicSharedMemorySize, GEMM_SMEM_BYTES);
    cudaFuncSetAttribute((const void*)mma_gemm<0,XSPLIT>,
        cudaFuncAttributeMaxDynamicSharedMemorySize, GEMM_SMEM_BYTES);
    cudaFuncSetAttribute((const void*)mma_gemm<1,1>,
        cudaFuncAttributeMaxDynamicSharedMemorySize, GEMM_SMEM_BYTES);
    cudaFuncSetAttribute((const void*)mma_gemm<0,OSPLIT>,
        cudaFuncAttributeMaxDynamicSharedMemorySize, GEMM_SMEM_BYTES);

    cudaMemcpyAsync(xb, u, sizeof(float) * (size_t)Tt * Hd, cudaMemcpyDeviceToDevice);

    const int TDN = Tt * DIN;
    dim3 blk256(256);

    for (int l = 0; l < LNUM; l++) {
        const float* ipw = in_proj_w + (size_t)l * D2 * Hd;
        const float* cw  = conv_w   + (size_t)l * DIN * Kc4;
        const float* cb  = conv_b   + (size_t)l * DIN;
        const float* xpw = x_proj_w + (size_t)l * XDBW * DIN;
        const float* dpw = dt_proj_w+ (size_t)l * DIN * Rr;
        const float* dpb = dt_proj_b+ (size_t)l * DIN;
        const float* Al  = A_log    + (size_t)l * DIN * Nst;
        const float* Dl  = D_w      + (size_t)l * DIN;
        const float* opw = out_proj_w + (size_t)l * Hd * DIN;
        const float* csl = conv_st  + (size_t)l * TDN * Kc4;
        const float* ssl = ssm_st   + (size_t)l * TDN * Nst;
        float* ocl = out_conv + (size_t)l * TDN * Kc4;
        float* osl = out_ssm  + (size_t)l * TDN * Nst;

        // 1. hn = rmsnorm(x)
        rmsnorm_kernel<<<Tt, 256>>>(xb, norm_w + (size_t)l * Hd, hnb);

        // 2. proj = hn @ in_proj_w^T   (1024 x 3072 x 768), 384 CTAs
        mma_gemm<0,1><<<dim3(D2/64, Tt/128, 1), blk256, GEMM_SMEM_BYTES>>>(
            hnb, Hd, ipw, Hd, projb, D2, Tt, D2, Hd, nullptr);

        // 3. conv shift + silu -> g_hs ; writes new_conv
        conv_kernel<<<(TDN + 255) / 256, blk256>>>(csl, cw, cb, ocl);

        // 4. xdb = hs @ x_proj_w^T   (1024 x 80 x 1536), split-K 8 -> 128 CTAs
        mma_gemm<0,XSPLIT><<<dim3(2, Tt/128, XSPLIT), blk256, GEMM_SMEM_BYTES>>>(
            hsb, DIN, xpw, DIN, xdbp, XDBW, Tt, XDBW, DIN, nullptr);
        reduce_xdb_kernel<<<(Tt*XDBW + 255)/256, blk256>>>(xdbb);

        // 5. dt = softplus(xdb[:, :R] @ dt_proj_w^T + b)   (1024 x 1536 x 48)
        mma_gemm<1,1><<<dim3(DIN/64, Tt/128, 1), blk256, GEMM_SMEM_BYTES>>>(
            xdbb, XDBW, dpw, Rr, dtb, DIN, Tt, DIN, Rr, dpb);

        // 6. SSM update -> g_y ; writes new_ssm
        ssm_kernel<<<TDN / 256, blk256>>>(ssl, Al, Dl, osl);

        // 7. x += y @ out_proj_w^T   (1024 x 768 x 1536), split-K 4 -> 384 CTAs
        mma_gemm<0,OSPLIT><<<dim3(Hd/64, Tt/128, OSPLIT), blk256, GEMM_SMEM_BYTES>>>(
            yb, DIN, opw, DIN, opart, Hd, Tt, Hd, DIN, nullptr);
        reduce_addx_kernel<<<(Tt*Hd + 255)/256, blk256>>>(xb);
    }

    rmsnorm_kernel<<<Tt, 256>>>(xb, norm_f_w, out_x);
}

// round 6
// speedup vs baseline: 5.3412x; 1.8352x over previous
#include <cuda_runtime.h>
#include <cuda_bf16.h>
#include <cstdint>

// Problem constants
#define LNUM 2
#define Bsz 4
#define Pn  256
#define Hd  768
#define En  2
#define Nst 16
#define Kc4 4
#define DIN (En*Hd)          // 1536
#define Rr  48
#define Tt  (Bsz*Pn)         // 1024
#define D2  (2*DIN)          // 3072
#define XDBW (Rr + 2*Nst)    // 80

#define XSPLIT 12
#define OSPLIT 4

// Scratch (device globals; no allocation allowed)
__device__ float g_x   [Tt*Hd];
__device__ float g_hn  [Tt*Hd];
__device__ float g_proj[Tt*D2];
__device__ float g_hs  [Tt*DIN];
__device__ float g_xdb [Tt*XDBW];
__device__ float g_xdbp[XSPLIT*Tt*XDBW];
__device__ float g_opart[OSPLIT*Tt*Hd];
__device__ float g_dt  [Tt*DIN];
__device__ float g_y   [Tt*DIN];
__device__ float g_A   [LNUM*DIN*Nst];   // precomputed -exp(A_log)

// ---------------- A table prep (once per launch) ----------------
__global__ void prep_A_kernel(const float* __restrict__ A_log) {
    int i = blockIdx.x * blockDim.x + threadIdx.x;
    if (i < LNUM * DIN * Nst) g_A[i] = -__expf(A_log[i]);
}

// ---------------- fused (residual add) + RMSNorm ----------------
// NP: number of split-K partials of out_proj to fold into x first (0 or OSPLIT)
template<int NP>
__global__ void fused_add_rmsnorm(float* __restrict__ x,
                                  const float* __restrict__ part,
                                  const float* __restrict__ w,
                                  float* __restrict__ out) {
    int t = blockIdx.x;
    float v[3];
    float s = 0.f;
    #pragma unroll
    for (int j = 0; j < 3; j++) {
        int i = threadIdx.x + j * 256;
        float xv = x[(size_t)t * Hd + i];
        if (NP > 0) {
            #pragma unroll
            for (int p = 0; p < NP; p++)
                xv += part[(size_t)p * Tt * Hd + (size_t)t * Hd + i];
        }
        v[j] = xv;
        s += xv * xv;
    }
    __shared__ float sh[8];
    int lane = threadIdx.x & 31, wp = threadIdx.x >> 5;
    #pragma unroll
    for (int o = 16; o; o >>= 1) s += __shfl_down_sync(0xffffffffu, s, o);
    if (lane == 0) sh[wp] = s;
    __syncthreads();
    if (wp == 0) {
        float tot = (lane < 8) ? sh[lane] : 0.f;
        #pragma unroll
        for (int o = 4; o; o >>= 1) tot += __shfl_down_sync(0xffffffffu, tot, o);
        if (lane == 0) sh[0] = tot;
    }
    __syncthreads();
    float inv = rsqrtf(sh[0] / (float)Hd + 1e-5f);
    #pragma unroll
    for (int j = 0; j < 3; j++) {
        int i = threadIdx.x + j * 256;
        if (NP > 0) x[(size_t)t * Hd + i] = v[j];
        out[(size_t)t * Hd + i] = v[j] * inv * w[i];
    }
}

// ---------------- TF32 helpers ----------------
__device__ __forceinline__ uint32_t cvt_tf32(float x) {
    uint32_t r;
    asm("cvt.rna.tf32.f32 %0, %1;" : "=r"(r) : "f"(x));
    return r;
}
__device__ __forceinline__ void mma_tf32(float* c, const uint32_t* a, const uint32_t* b) {
    asm volatile("mma.sync.aligned.m16n8k8.row.col.f32.tf32.tf32.f32 "
        "{%0,%1,%2,%3}, {%4,%5,%6,%7}, {%8,%9}, {%0,%1,%2,%3};"
        : "+f"(c[0]), "+f"(c[1]), "+f"(c[2]), "+f"(c[3])
        : "r"(a[0]), "r"(a[1]), "r"(a[2]), "r"(a[3]), "r"(b[0]), "r"(b[1]));
}

// ---------------- Pipelined TF32 tensor-core GEMM: C = A(MxK) * B(NxK)^T ----
// Single-pass TF32 (rna). Block tile 128x64, BK=32, 256 threads,
// warp grid 4x2, warp tile 32x32. Double-buffered smem (55KB).
// MODE 0: store   MODE 1: softplus(v + bias[col])
// SPLITK>1: blockIdx.z selects K chunk; raw partial -> C + z*M*ldc (MODE 0)
#define APLANE (128*36)
#define BPLANE (64*36)
#define GEMM_SMEM_U32 (2*APLANE + 2*BPLANE)
#define GEMM_SMEM_BYTES (GEMM_SMEM_U32*4)

template<int MODE, int SPLITK>
__global__ void __launch_bounds__(256, 2)
mma_gemm(const float* __restrict__ A, int lda,
         const float* __restrict__ B, int ldb,
         float* __restrict__ C, int ldc,
         int M, int N, int K,
         const float* __restrict__ bias) {
    extern __shared__ uint32_t smem_u32[];
    uint32_t* AsT = smem_u32;                 // [2][128][36]
    uint32_t* BsT = smem_u32 + 2*APLANE;      // [2][64][36]

    int tid = threadIdx.x;
    int warp = tid >> 5, lane = tid & 31;
    int wm = warp >> 1, wn = warp & 1;        // 4 x 2 warps, warp tile 32x32
    int gid = lane >> 2, tig = lane & 3;

    int bm = blockIdx.y * 128, bn = blockIdx.x * 64;

    int kbeg = 0, kend = K;
    if (SPLITK > 1) {
        int chunk = K / SPLITK;
        kbeg = blockIdx.z * chunk;
        kend = kbeg + chunk;
        C += (size_t)blockIdx.z * M * ldc;
    }

    float acc[2][4][4];
    #pragma unroll
    for (int i = 0; i < 2; i++)
        #pragma unroll
        for (int j = 0; j < 4; j++)
            #pragma unroll
            for (int q = 0; q < 4; q++) acc[i][j][q] = 0.f;

    int lr = tid >> 3;            // 0..31
    int lc = (tid & 7) * 4;       // 0,4,...,28

    float4 ra[4], rb[2];

    auto load_regs = [&](int k0) {
        #pragma unroll
        for (int p = 0; p < 4; p++) {
            int grow = bm + lr + p * 32;
            int kc = k0 + lc;
            float4 v = make_float4(0.f, 0.f, 0.f, 0.f);
            if (grow < M) {
                const float* pA = A + (size_t)grow * lda + kc;
                if (kc + 3 < kend) v = *(const float4*)pA;
                else {
                    if (kc + 0 < kend) v.x = pA[0];
                    if (kc + 1 < kend) v.y = pA[1];
                    if (kc + 2 < kend) v.z = pA[2];
                    if (kc + 3 < kend) v.w = pA[3];
                }
            }
            ra[p] = v;
        }
        #pragma unroll
        for (int p = 0; p < 2; p++) {
            int grow = bn + lr + p * 32;
            int kc = k0 + lc;
            float4 v = make_float4(0.f, 0.f, 0.f, 0.f);
            if (grow < N) {
                const float* pB = B + (size_t)grow * ldb + kc;
                if (kc + 3 < kend) v = *(const float4*)pB;
                else {
                    if (kc + 0 < kend) v.x = pB[0];
                    if (kc + 1 < kend) v.y = pB[1];
                    if (kc + 2 < kend) v.z = pB[2];
                    if (kc + 3 < kend) v.w = pB[3];
                }
            }
            rb[p] = v;
        }
    };

    auto store_cvt = [&](int buf) {
        #pragma unroll
        for (int p = 0; p < 4; p++) {
            int row = lr + p * 32;
            int off = buf*APLANE + row*36 + lc;
            *(uint4*)&AsT[off] = make_uint4(cvt_tf32(ra[p].x), cvt_tf32(ra[p].y),
                                            cvt_tf32(ra[p].z), cvt_tf32(ra[p].w));
        }
        #pragma unroll
        for (int p = 0; p < 2; p++) {
            int row = lr + p * 32;
            int off = buf*BPLANE + row*36 + lc;
            *(uint4*)&BsT[off] = make_uint4(cvt_tf32(rb[p].x), cvt_tf32(rb[p].y),
                                            cvt_tf32(rb[p].z), cvt_tf32(rb[p].w));
        }
    };

    auto compute = [&](int buf) {
        #pragma unroll
        for (int ks = 0; ks < 4; ks++) {
            int kk = ks * 8;
            uint32_t af[2][4];
            #pragma unroll
            for (int mt = 0; mt < 2; mt++) {
                int m = wm * 32 + mt * 16 + gid;
                int o = buf*APLANE + m*36 + kk + tig;
                af[mt][0] = AsT[o];
                af[mt][1] = AsT[o + 8*36];
                af[mt][2] = AsT[o + 4];
                af[mt][3] = AsT[o + 8*36 + 4];
            }
            uint32_t bf[4][2];
            #pragma unroll
            for (int nt = 0; nt < 4; nt++) {
                int n = wn * 32 + nt * 8 + gid;
                int o = buf*BPLANE + n*36 + kk + tig;
                bf[nt][0] = BsT[o];
                bf[nt][1] = BsT[o + 4];
            }
            #pragma unroll
            for (int mt = 0; mt < 2; mt++)
                #pragma unroll
                for (int nt = 0; nt < 4; nt++)
                    mma_tf32(acc[mt][nt], af[mt], bf[nt]);
        }
    };

    int nk = (kend - kbeg + 31) >> 5;

    load_regs(kbeg);
    store_cvt(0);

    for (int it = 0; it < nk; it++) {
        int cur = it & 1;
        if (it + 1 < nk) load_regs(kbeg + (it + 1) * 32);
        __syncthreads();
        compute(cur);
        if (it + 1 < nk) store_cvt(cur ^ 1);
    }

    // Epilogue
    #pragma unroll
    for (int mt = 0; mt < 2; mt++) {
        #pragma unroll
        for (int nt = 0; nt < 4; nt++) {
            #pragma unroll
            for (int q = 0; q < 4; q++) {
                int row = bm + wm * 32 + mt * 16 + gid + ((q >> 1) ? 8 : 0);
                int col = bn + wn * 32 + nt * 8 + 2 * tig + (q & 1);
                if (row >= M || col >= N) continue;
                size_t o = (size_t)row * ldc + col;
                float v = acc[mt][nt][q];
                if (MODE == 0) {
                    C[o] = v;
                } else {
                    v += bias[col];
                    // stable fast softplus
                    float sp = (v > 0.f) ? v + __logf(1.f + __expf(-v))
                                         : __logf(1.f + __expf(v));
                    C[o] = sp;
                }
            }
        }
    }
}

// ---------------- split-K reduction for xdb ----------------
__global__ void reduce_xdb_kernel(float* __restrict__ out) {
    int i = blockIdx.x * blockDim.x + threadIdx.x;
    const int SZ = Tt * XDBW;
    if (i < SZ) {
        float s = 0.f;
        #pragma unroll
        for (int p = 0; p < XSPLIT; p++) s += g_xdbp[i + p * SZ];
        out[i] = s;
    }
}

// ---------------- Conv shift + silu ----------------
__global__ void conv_kernel(const float* __restrict__ conv_states_l,
                            const float* __restrict__ conv_w_l,
                            const float* __restrict__ conv_b_l,
                            float* __restrict__ out_conv_l) {
    int idx = blockIdx.x * blockDim.x + threadIdx.x;
    if (idx >= Tt * DIN) return;
    int t = idx / DIN, d = idx - t * DIN;
    float4 cs = *(const float4*)(conv_states_l + (size_t)idx * 4);
    float hsv = g_proj[(size_t)t * D2 + d];
    float4 nc = make_float4(cs.y, cs.z, cs.w, hsv);
    *(float4*)(out_conv_l + (size_t)idx * 4) = nc;
    float4 w = *(const float4*)(conv_w_l + (size_t)d * 4);
    float s = nc.x * w.x + nc.y * w.y + nc.z * w.z + nc.w * w.w + conv_b_l[d];
    g_hs[idx] = s / (1.f + __expf(-s));
}

// ---------------- SSM state update + gated output ----------------
__global__ void ssm_kernel(const float* __restrict__ ssm_l,
                           const float* __restrict__ A_pre,   // -exp(A_log), this layer
                           const float* __restrict__ D_l,
                           float* __restrict__ out_ssm_l) {
    __shared__ float Bsh[Nst], Csh[Nst];
    int idx = blockIdx.x * 256 + threadIdx.x;
    int t = idx / DIN, d = idx - t * DIN;
    if (threadIdx.x < 2 * Nst) {
        float v = g_xdb[(size_t)t * XDBW + Rr + threadIdx.x];
        if (threadIdx.x < Nst) Bsh[threadIdx.x] = v;
        else Csh[threadIdx.x - Nst] = v;
    }
    __syncthreads();
    float dtv = g_dt[idx];
    float hsv = g_hs[idx];
    float dh  = dtv * hsv;
    const float4* Ar4 = (const float4*)(A_pre + (size_t)d * Nst);
    const float4* sr4 = (const float4*)(ssm_l + (size_t)idx * Nst);
    float4* so4 = (float4*)(out_ssm_l + (size_t)idx * Nst);
    float y = 0.f;
    #pragma unroll
    for (int q = 0; q < 4; q++) {
        float4 a = Ar4[q];
        float4 s = sr4[q];
        float4 r;
        r.x = s.x * __expf(dtv * a.x) + dh * Bsh[q*4+0];
        r.y = s.y * __expf(dtv * a.y) + dh * Bsh[q*4+1];
        r.z = s.z * __expf(dtv * a.z) + dh * Bsh[q*4+2];
        r.w = s.w * __expf(dtv * a.w) + dh * Bsh[q*4+3];
        so4[q] = r;
        y += r.x * Csh[q*4+0] + r.y * Csh[q*4+1] + r.z * Csh[q*4+2] + r.w * Csh[q*4+3];
    }
    y += D_l[d] * hsv;
    float g = g_proj[(size_t)t * D2 + DIN + d];
    y *= g / (1.f + __expf(-g));
    g_y[idx] = y;
}

extern "C" void kernel_launch(void* const* d_in, const int* in_sizes, int n_in,
                              void* d_out, int out_size) {
    const float* u          = (const float*)d_in[0];
    const float* conv_st    = (const float*)d_in[1];
    const float* ssm_st     = (const float*)d_in[2];
    const float* in_proj_w  = (const float*)d_in[3];
    const float* conv_w     = (const float*)d_in[4];
    const float* conv_b     = (const float*)d_in[5];
    const float* x_proj_w   = (const float*)d_in[6];
    const float* dt_proj_w  = (const float*)d_in[7];
    const float* dt_proj_b  = (const float*)d_in[8];
    const float* A_log      = (const float*)d_in[9];
    const float* D_w        = (const float*)d_in[10];
    const float* out_proj_w = (const float*)d_in[11];
    const float* norm_w     = (const float*)d_in[12];
    const float* norm_f_w   = (const float*)d_in[13];

    float* out_x    = (float*)d_out;
    float* out_conv = out_x + (size_t)Tt * Hd;
    float* out_ssm  = out_conv + (size_t)LNUM * Tt * DIN * Kc4;

    float *xb, *hnb, *projb, *hsb, *xdbb, *xdbp, *opart, *dtb, *yb, *Ab;
    cudaGetSymbolAddress((void**)&xb,    g_x);
    cudaGetSymbolAddress((void**)&hnb,   g_hn);
    cudaGetSymbolAddress((void**)&projb, g_proj);
    cudaGetSymbolAddress((void**)&hsb,   g_hs);
    cudaGetSymbolAddress((void**)&xdbb,  g_xdb);
    cudaGetSymbolAddress((void**)&xdbp,  g_xdbp);
    cudaGetSymbolAddress((void**)&opart, g_opart);
    cudaGetSymbolAddress((void**)&dtb,   g_dt);
    cudaGetSymbolAddress((void**)&yb,    g_y);
    cudaGetSymbolAddress((void**)&Ab,    g_A);

    cudaFuncSetAttribute((const void*)mma_gemm<0,1>,
        cudaFuncAttributeMaxDynamicSharedMemorySize, GEMM_SMEM_BYTES);
    cudaFuncSetAttribute((const void*)mma_gemm<0,XSPLIT>,
        cudaFuncAttributeMaxDynamicSharedMemorySize, GEMM_SMEM_BYTES);
    cudaFuncSetAttribute((const void*)mma_gemm<1,1>,
        cudaFuncAttributeMaxDynamicSharedMemorySize, GEMM_SMEM_BYTES);
    cudaFuncSetAttribute((const void*)mma_gemm<0,OSPLIT>,
        cudaFuncAttributeMaxDynamicSharedMemorySize, GEMM_SMEM_BYTES);

    cudaMemcpyAsync(xb, u, sizeof(float) * (size_t)Tt * Hd, cudaMemcpyDeviceToDevice);
    prep_A_kernel<<<(LNUM*DIN*Nst + 255)/256, 256>>>(A_log);

    const int TDN = Tt * DIN;
    dim3 blk256(256);

    for (int l = 0; l < LNUM; l++) {
        const float* ipw = in_proj_w + (size_t)l * D2 * Hd;
        const float* cw  = conv_w   + (size_t)l * DIN * Kc4;
        const float* cb  = conv_b   + (size_t)l * DIN;
        const float* xpw = x_proj_w + (size_t)l * XDBW * DIN;
        const float* dpw = dt_proj_w+ (size_t)l * DIN * Rr;
        const float* dpb = dt_proj_b+ (size_t)l * DIN;
        const float* Al  = Ab       + (size_t)l * DIN * Nst;
        const float* Dl  = D_w      + (size_t)l * DIN;
        const float* opw = out_proj_w + (size_t)l * Hd * DIN;
        const float* csl = conv_st  + (size_t)l * TDN * Kc4;
        const float* ssl = ssm_st   + (size_t)l * TDN * Nst;
        float* ocl = out_conv + (size_t)l * TDN * Kc4;
        float* osl = out_ssm  + (size_t)l * TDN * Nst;

        // 1. (residual add for l>0) + rmsnorm -> hn
        if (l == 0)
            fused_add_rmsnorm<0><<<Tt, 256>>>(xb, nullptr, norm_w + (size_t)l * Hd, hnb);
        else
            fused_add_rmsnorm<OSPLIT><<<Tt, 256>>>(xb, opart, norm_w + (size_t)l * Hd, hnb);

        // 2. proj = hn @ in_proj_w^T   (1024 x 3072 x 768), 384 CTAs
        mma_gemm<0,1><<<dim3(D2/64, Tt/128, 1), blk256, GEMM_SMEM_BYTES>>>(
            hnb, Hd, ipw, Hd, projb, D2, Tt, D2, Hd, nullptr);

        // 3. conv shift + silu -> g_hs ; writes new_conv
        conv_kernel<<<(TDN + 255) / 256, blk256>>>(csl, cw, cb, ocl);

        // 4. xdb = hs @ x_proj_w^T   (1024 x 80 x 1536), split-K 12 -> 192 CTAs
        mma_gemm<0,XSPLIT><<<dim3(2, Tt/128, XSPLIT), blk256, GEMM_SMEM_BYTES>>>(
            hsb, DIN, xpw, DIN, xdbp, XDBW, Tt, XDBW, DIN, nullptr);
        reduce_xdb_kernel<<<(Tt*XDBW + 255)/256, blk256>>>(xdbb);

        // 5. dt = softplus(xdb[:, :R] @ dt_proj_w^T + b)   (1024 x 1536 x 48)
        mma_gemm<1,1><<<dim3(DIN/64, Tt/128, 1), blk256, GEMM_SMEM_BYTES>>>(
            xdbb, XDBW, dpw, Rr, dtb, DIN, Tt, DIN, Rr, dpb);

        // 6. SSM update -> g_y ; writes new_ssm
        ssm_kernel<<<TDN / 256, blk256>>>(ssl, Al, Dl, osl);

        // 7. x += y @ out_proj_w^T   (1024 x 768 x 1536), split-K 4 -> 384 CTAs
        //    partials folded into x by next fused_add_rmsnorm
        mma_gemm<0,OSPLIT><<<dim3(Hd/64, Tt/128, OSPLIT), blk256, GEMM_SMEM_BYTES>>>(
            yb, DIN, opw, DIN, opart, Hd, Tt, Hd, DIN, nullptr);
    }

    // final: fold layer-1 partials into x, then rmsnorm with norm_f_w -> out_x
    fused_add_rmsnorm<OSPLIT><<<Tt, 256>>>(xb, opart, norm_f_w, out_x);
}